// round 2
// baseline (speedup 1.0000x reference)
#include <cuda_runtime.h>
#include <math.h>
#include <stdint.h>

#define N_ELEM 4194304  // 4*1024*1024 = H*B*S*DK

// ---------------- scratch (device globals; no runtime allocation) ----------
__device__ float  g_q [N_ELEM];
__device__ float  g_kT[N_ELEM];
__device__ float  g_v [N_ELEM];
__device__ float  g_o2[N_ELEM];
__device__ float  g_t1[N_ELEM];
__device__ float  g_n1[N_ELEM];
__device__ float  g_n2[N_ELEM];
__device__ float  g_fc1[4096 * 2048];
__device__ double g_part[256][2];
__device__ float  g_stats[4][2];   // [b] {mean, invstd}

// ---------------- generic fp32 SGEMM: C = A[M,K] * B[K,N] (+bias,+res,relu) --
template<bool BIAS, bool RES, bool RELU>
__global__ __launch_bounds__(256, 2)
void sgemm_kernel(const float* __restrict__ A, const float* __restrict__ B,
                  const float* __restrict__ bias, const float* __restrict__ res,
                  float* __restrict__ C, int M, int N, int K)
{
    __shared__ float As[16][128];
    __shared__ float Bs[16][128];
    const int tid = threadIdx.x;
    const int tx = tid & 15, ty = tid >> 4;
    const int m0 = blockIdx.y << 7, n0 = blockIdx.x << 7;
    const int aRow = tid >> 2, aCol = (tid & 3) << 2;
    const int bRow = tid >> 5, bCol = (tid & 31) << 2;

    float acc[8][8];
#pragma unroll
    for (int i = 0; i < 8; i++)
#pragma unroll
        for (int j = 0; j < 8; j++) acc[i][j] = 0.f;

    for (int k0 = 0; k0 < K; k0 += 16) {
#pragma unroll
        for (int r = 0; r < 2; r++) {
            float4 a = *(const float4*)(A + (size_t)(m0 + aRow + (r << 6)) * K + (k0 + aCol));
            As[aCol + 0][aRow + (r << 6)] = a.x;
            As[aCol + 1][aRow + (r << 6)] = a.y;
            As[aCol + 2][aRow + (r << 6)] = a.z;
            As[aCol + 3][aRow + (r << 6)] = a.w;
        }
#pragma unroll
        for (int r = 0; r < 2; r++) {
            *(float4*)&Bs[bRow + (r << 3)][bCol] =
                *(const float4*)(B + (size_t)(k0 + bRow + (r << 3)) * N + (n0 + bCol));
        }
        __syncthreads();
#pragma unroll
        for (int kk = 0; kk < 16; kk++) {
            float af[8], bf[8];
            *(float4*)&af[0] = *(const float4*)&As[kk][(ty << 3)];
            *(float4*)&af[4] = *(const float4*)&As[kk][(ty << 3) + 4];
            *(float4*)&bf[0] = *(const float4*)&Bs[kk][(tx << 3)];
            *(float4*)&bf[4] = *(const float4*)&Bs[kk][(tx << 3) + 4];
#pragma unroll
            for (int i = 0; i < 8; i++)
#pragma unroll
                for (int j = 0; j < 8; j++)
                    acc[i][j] = fmaf(af[i], bf[j], acc[i][j]);
        }
        __syncthreads();
    }

#pragma unroll
    for (int i = 0; i < 8; i++) {
        const int m = m0 + (ty << 3) + i;
#pragma unroll
        for (int j = 0; j < 8; j += 4) {
            const int n = n0 + (tx << 3) + j;
            float4 v = make_float4(acc[i][j], acc[i][j + 1], acc[i][j + 2], acc[i][j + 3]);
            if (BIAS) {
                float4 bv = *(const float4*)(bias + n);
                v.x += bv.x; v.y += bv.y; v.z += bv.z; v.w += bv.w;
            }
            if (RES) {
                float4 rv = *(const float4*)(res + (size_t)m * N + n);
                v.x += rv.x; v.y += rv.y; v.z += rv.z; v.w += rv.w;
            }
            if (RELU) {
                v.x = fmaxf(v.x, 0.f); v.y = fmaxf(v.y, 0.f);
                v.z = fmaxf(v.z, 0.f); v.w = fmaxf(v.w, 0.f);
            }
            *(float4*)(C + (size_t)m * N + n) = v;
        }
    }
}

// ---------------- projection GEMM: Y[h,b,s,d] = sum_e X[b,s,e] * W[h,e,d] ----
// M=4096 rows (b*1024+s), N=1024 cols (h*64+d), K=1024.
// mode 0: write standard layout [hb][s][d] (q, v)
// mode 1: write kT layout: t=(s&15)*64+d, dcol=s>>4  ->  [hb][t][dcol]
__global__ __launch_bounds__(256, 2)
void proj_kernel(const float* __restrict__ X, const float* __restrict__ W,
                 float* __restrict__ Y, int mode)
{
    __shared__ float As[16][128];
    __shared__ float Bs[16][128];
    const int tid = threadIdx.x;
    const int tx = tid & 15, ty = tid >> 4;
    const int m0 = blockIdx.y << 7, n0 = blockIdx.x << 7;
    const int aRow = tid >> 2, aCol = (tid & 3) << 2;
    const int bRow = tid >> 5, bCol = (tid & 31) << 2;

    float acc[8][8];
#pragma unroll
    for (int i = 0; i < 8; i++)
#pragma unroll
        for (int j = 0; j < 8; j++) acc[i][j] = 0.f;

    for (int k0 = 0; k0 < 1024; k0 += 16) {
#pragma unroll
        for (int r = 0; r < 2; r++) {
            float4 a = *(const float4*)(X + (size_t)(m0 + aRow + (r << 6)) * 1024 + (k0 + aCol));
            As[aCol + 0][aRow + (r << 6)] = a.x;
            As[aCol + 1][aRow + (r << 6)] = a.y;
            As[aCol + 2][aRow + (r << 6)] = a.z;
            As[aCol + 3][aRow + (r << 6)] = a.w;
        }
#pragma unroll
        for (int r = 0; r < 2; r++) {
            const int n = n0 + bCol;
            const int k = k0 + bRow + (r << 3);
            // W'[k][n] = W[(n>>6)*E*DK + k*DK + (n&63)]; 4 consecutive n stay in one h-group
            *(float4*)&Bs[bRow + (r << 3)][bCol] =
                *(const float4*)(W + ((size_t)(n >> 6) << 16) + ((size_t)k << 6) + (n & 63));
        }
        __syncthreads();
#pragma unroll
        for (int kk = 0; kk < 16; kk++) {
            float af[8], bf[8];
            *(float4*)&af[0] = *(const float4*)&As[kk][(ty << 3)];
            *(float4*)&af[4] = *(const float4*)&As[kk][(ty << 3) + 4];
            *(float4*)&bf[0] = *(const float4*)&Bs[kk][(tx << 3)];
            *(float4*)&bf[4] = *(const float4*)&Bs[kk][(tx << 3) + 4];
#pragma unroll
            for (int i = 0; i < 8; i++)
#pragma unroll
                for (int j = 0; j < 8; j++)
                    acc[i][j] = fmaf(af[i], bf[j], acc[i][j]);
        }
        __syncthreads();
    }

#pragma unroll
    for (int i = 0; i < 8; i++) {
        const int m = m0 + (ty << 3) + i;
        const int b = m >> 10, s = m & 1023;
#pragma unroll
        for (int j = 0; j < 8; j += 4) {
            const int n = n0 + (tx << 3) + j;
            const int h = n >> 6, d = n & 63;
            const size_t hb = (size_t)(h * 4 + b);
            if (mode == 0) {
                // d..d+3 contiguous within the same head group (d <= 60 here)
                float4 v = make_float4(acc[i][j], acc[i][j + 1], acc[i][j + 2], acc[i][j + 3]);
                *(float4*)(Y + ((hb << 10) + s) * 64 + d) = v;
            } else {
#pragma unroll
                for (int jj = 0; jj < 4; jj++) {
                    const int t = ((s & 15) << 6) | (d + jj);
                    Y[((hb << 10) + t) * 64 + (s >> 4)] = acc[i][j + jj];
                }
            }
        }
    }
}

// ---------------- fused flash attention (fp32, optional causal mask) --------
// grid (16 s-tiles, 64 hb). score(s,t)=dot64(Q[s],KT[t]); softmax(score/8);
// out = P*V; scatter-write into "out2" concat layout.
__global__ __launch_bounds__(256)
void flash_kernel(const float* __restrict__ Q, const float* __restrict__ KT,
                  const float* __restrict__ V, float* __restrict__ O2, int causal)
{
    extern __shared__ float sm[];
    float* Qd = sm;                 // [64][68]  (d-major: Qd[d][r])
    float* KP = sm + 64 * 68;       // Kd[d][c] during scores, Ps[t][r] during PV
    float* Vs = sm + 2 * 64 * 68;   // [t][dv], stride 68

    const int tid = threadIdx.x;
    const int tx = tid & 15, ty = tid >> 4;
    const int s0 = blockIdx.x << 6;
    const int hb = blockIdx.y;
    const size_t base = (size_t)hb << 16;

    const int lr = tid >> 2;
    const int ld4 = (tid & 3) << 4;

    // load Q tile transposed into Qd[d][r]
#pragma unroll
    for (int c = 0; c < 16; c += 4) {
        float4 qv = *(const float4*)(Q + base + ((size_t)(s0 + lr) << 6) + ld4 + c);
        Qd[(ld4 + c + 0) * 68 + lr] = qv.x;
        Qd[(ld4 + c + 1) * 68 + lr] = qv.y;
        Qd[(ld4 + c + 2) * 68 + lr] = qv.z;
        Qd[(ld4 + c + 3) * 68 + lr] = qv.w;
    }

    float o[4][4], m[4], l[4];
#pragma unroll
    for (int i = 0; i < 4; i++) {
        m[i] = -INFINITY; l[i] = 0.f;
#pragma unroll
        for (int j = 0; j < 4; j++) o[i][j] = 0.f;
    }

    const int ntiles = causal ? ((int)blockIdx.x + 1) : 16;
    for (int jt = 0; jt < ntiles; jt++) {
        const int t0 = jt << 6;
        __syncthreads();  // previous PV / Q-load complete before overwriting KP/Vs
#pragma unroll
        for (int c = 0; c < 16; c += 4) {
            float4 kv = *(const float4*)(KT + base + ((size_t)(t0 + lr) << 6) + ld4 + c);
            KP[(ld4 + c + 0) * 68 + lr] = kv.x;
            KP[(ld4 + c + 1) * 68 + lr] = kv.y;
            KP[(ld4 + c + 2) * 68 + lr] = kv.z;
            KP[(ld4 + c + 3) * 68 + lr] = kv.w;
            float4 vv = *(const float4*)(V + base + ((size_t)(t0 + lr) << 6) + ld4 + c);
            *(float4*)&Vs[lr * 68 + ld4 + c] = vv;
        }
        __syncthreads();

        // scores: 4x4 per thread (rows 4ty.., cols 4tx..)
        float sc[4][4];
#pragma unroll
        for (int i = 0; i < 4; i++)
#pragma unroll
            for (int j = 0; j < 4; j++) sc[i][j] = 0.f;
#pragma unroll 16
        for (int d = 0; d < 64; d++) {
            float4 qv = *(const float4*)&Qd[d * 68 + (ty << 2)];
            float4 kv = *(const float4*)&KP[d * 68 + (tx << 2)];
            const float qa[4] = {qv.x, qv.y, qv.z, qv.w};
            const float ka[4] = {kv.x, kv.y, kv.z, kv.w};
#pragma unroll
            for (int i = 0; i < 4; i++)
#pragma unroll
                for (int j = 0; j < 4; j++)
                    sc[i][j] = fmaf(qa[i], ka[j], sc[i][j]);
        }
        __syncthreads();  // all done reading Kd before it becomes Ps

        // online softmax update
        float p[4][4];
#pragma unroll
        for (int i = 0; i < 4; i++) {
            const int srow = s0 + (ty << 2) + i;
            float mx = -INFINITY;
#pragma unroll
            for (int j = 0; j < 4; j++) {
                float v = sc[i][j] * 0.125f;
                if (causal && (t0 + (tx << 2) + j > srow)) v = -INFINITY;
                sc[i][j] = v;
                mx = fmaxf(mx, v);
            }
            mx = fmaxf(mx, __shfl_xor_sync(0xffffffffu, mx, 1));
            mx = fmaxf(mx, __shfl_xor_sync(0xffffffffu, mx, 2));
            mx = fmaxf(mx, __shfl_xor_sync(0xffffffffu, mx, 4));
            mx = fmaxf(mx, __shfl_xor_sync(0xffffffffu, mx, 8));
            const float mnew = fmaxf(m[i], mx);
            const float corr = __expf(m[i] - mnew);
            m[i] = mnew;
            float rs = 0.f;
#pragma unroll
            for (int j = 0; j < 4; j++) {
                const float pe = __expf(sc[i][j] - mnew);
                p[i][j] = pe;
                rs += pe;
            }
            rs += __shfl_xor_sync(0xffffffffu, rs, 1);
            rs += __shfl_xor_sync(0xffffffffu, rs, 2);
            rs += __shfl_xor_sync(0xffffffffu, rs, 4);
            rs += __shfl_xor_sync(0xffffffffu, rs, 8);
            l[i] = l[i] * corr + rs;
#pragma unroll
            for (int j = 0; j < 4; j++) o[i][j] *= corr;
        }

        // store P into KP as Ps[t][r] (vectorized along r)
#pragma unroll
        for (int j = 0; j < 4; j++) {
            float4 pv = make_float4(p[0][j], p[1][j], p[2][j], p[3][j]);
            *(float4*)&KP[((tx << 2) + j) * 68 + (ty << 2)] = pv;
        }
        __syncthreads();

        // PV: out[r][dv] += P[r][t] * V[t][dv]
#pragma unroll 16
        for (int t = 0; t < 64; t++) {
            float4 pf = *(const float4*)&KP[t * 68 + (ty << 2)];
            float4 vf = *(const float4*)&Vs[t * 68 + (tx << 2)];
            const float pa[4] = {pf.x, pf.y, pf.z, pf.w};
            const float va[4] = {vf.x, vf.y, vf.z, vf.w};
#pragma unroll
            for (int i = 0; i < 4; i++)
#pragma unroll
                for (int j = 0; j < 4; j++)
                    o[i][j] = fmaf(pa[i], va[j], o[i][j]);
        }
    }

    // epilogue: scatter into out2 concat layout
    const int h = hb >> 2, b = hb & 3;
#pragma unroll
    for (int i = 0; i < 4; i++) {
        const int s = s0 + (ty << 2) + i;
        const float invl = 1.f / l[i];
        const size_t row = ((size_t)((h >> 2) * 1024 + (h & 3) * 256 + b * 64 + (s >> 4)) << 10)
                         + ((s & 15) << 6);
        float4 ov = make_float4(o[i][0] * invl, o[i][1] * invl, o[i][2] * invl, o[i][3] * invl);
        *(float4*)(O2 + row + (tx << 2)) = ov;
    }
}

// ---------------- LayerNorm over whole (S,E) slab per batch -----------------
__global__ void ln_part_kernel(const float* __restrict__ X)
{
    __shared__ double sd[256];
    __shared__ double sq[256];
    const int tid = threadIdx.x;
    const float4* p = (const float4*)(X + ((size_t)blockIdx.x << 14));
    float s = 0.f, q = 0.f;
#pragma unroll
    for (int it = 0; it < 16; it++) {
        float4 v = p[it * 256 + tid];
        s += v.x + v.y + v.z + v.w;
        q += v.x * v.x + v.y * v.y + v.z * v.z + v.w * v.w;
    }
    sd[tid] = (double)s; sq[tid] = (double)q;
    __syncthreads();
    for (int off = 128; off > 0; off >>= 1) {
        if (tid < off) { sd[tid] += sd[tid + off]; sq[tid] += sq[tid + off]; }
        __syncthreads();
    }
    if (tid == 0) { g_part[blockIdx.x][0] = sd[0]; g_part[blockIdx.x][1] = sq[0]; }
}

__global__ void ln_final_kernel()
{
    const int b = threadIdx.x;
    if (b < 4) {
        double s = 0.0, q = 0.0;
        for (int i = 0; i < 64; i++) { s += g_part[b * 64 + i][0]; q += g_part[b * 64 + i][1]; }
        const double inv_n = 1.0 / 1048576.0;
        const double mean = s * inv_n;
        const double var = q * inv_n - mean * mean;
        g_stats[b][0] = (float)mean;
        g_stats[b][1] = (float)(1.0 / sqrt(var + 1e-5));
    }
}

__global__ void ln_apply_kernel(const float* __restrict__ X, const float* __restrict__ w,
                                const float* __restrict__ bb, float* __restrict__ Y)
{
    const size_t i = ((size_t)blockIdx.x * 256 + threadIdx.x) << 2;
    const int b = (int)(i >> 20);
    const float mean = g_stats[b][0], inv = g_stats[b][1];
    const size_t wi = i & 1048575;
    float4 x = *(const float4*)(X + i);
    float4 wv = *(const float4*)(w + wi);
    float4 bv = *(const float4*)(bb + wi);
    float4 y;
    y.x = (x.x - mean) * inv * wv.x + bv.x;
    y.y = (x.y - mean) * inv * wv.y + bv.y;
    y.z = (x.z - mean) * inv * wv.z + bv.z;
    y.w = (x.w - mean) * inv * wv.w + bv.w;
    *(float4*)(Y + i) = y;
}

// ---------------- driver ----------------------------------------------------
extern "C" void kernel_launch(void* const* d_in, const int* in_sizes, int n_in,
                              void* d_out, int out_size)
{
    const float* inputRes = (const float*)d_in[0];
    const float* outEnc   = (const float*)d_in[1];
    const float* Wq1 = (const float*)d_in[2];
    const float* Wk1 = (const float*)d_in[3];
    const float* Wv1 = (const float*)d_in[4];
    const float* Wo1 = (const float*)d_in[5];
    const float* Wq2 = (const float*)d_in[6];
    const float* Wk2 = (const float*)d_in[7];
    const float* Wv2 = (const float*)d_in[8];
    const float* Wo2 = (const float*)d_in[9];
    const float* ln1w = (const float*)d_in[10];
    const float* ln1b = (const float*)d_in[11];
    const float* ln2w = (const float*)d_in[12];
    const float* ln2b = (const float*)d_in[13];
    const float* ln3w = (const float*)d_in[14];
    const float* ln3b = (const float*)d_in[15];
    const float* W1 = (const float*)d_in[16];
    const float* b1 = (const float*)d_in[17];
    const float* W2 = (const float*)d_in[18];
    const float* b2 = (const float*)d_in[19];
    float* out = (float*)d_out;

    float *q, *kT, *v, *o2, *t1, *n1, *n2, *fc1;
    cudaGetSymbolAddress((void**)&q,   g_q);
    cudaGetSymbolAddress((void**)&kT,  g_kT);
    cudaGetSymbolAddress((void**)&v,   g_v);
    cudaGetSymbolAddress((void**)&o2,  g_o2);
    cudaGetSymbolAddress((void**)&t1,  g_t1);
    cudaGetSymbolAddress((void**)&n1,  g_n1);
    cudaGetSymbolAddress((void**)&n2,  g_n2);
    cudaGetSymbolAddress((void**)&fc1, g_fc1);

    const int FLASH_SMEM = 3 * 64 * 68 * 4;  // 52224 B
    cudaFuncSetAttribute(flash_kernel, cudaFuncAttributeMaxDynamicSharedMemorySize, FLASH_SMEM);

    dim3 gp(8, 32), blk(256);

    // ---- MHA1 (self, causal): x_kv = x_q = outputEncoding ----
    proj_kernel<<<gp, blk>>>(outEnc, Wq1, q, 0);
    proj_kernel<<<gp, blk>>>(outEnc, Wk1, kT, 1);
    proj_kernel<<<gp, blk>>>(outEnc, Wv1, v, 0);
    flash_kernel<<<dim3(16, 64), blk, FLASH_SMEM>>>(q, kT, v, o2, 1);
    sgemm_kernel<false, true, false><<<dim3(8, 32), blk>>>(o2, Wo1, nullptr, outEnc, t1, 4096, 1024, 1024);
    ln_part_kernel<<<256, 256>>>(t1);
    ln_final_kernel<<<1, 32>>>();
    ln_apply_kernel<<<4096, 256>>>(t1, ln1w, ln1b, n1);

    // ---- MHA2 (cross): Q from att_norm, K/V from inputRes ----
    proj_kernel<<<gp, blk>>>(n1, Wq2, q, 0);
    proj_kernel<<<gp, blk>>>(inputRes, Wk2, kT, 1);
    proj_kernel<<<gp, blk>>>(inputRes, Wv2, v, 0);
    flash_kernel<<<dim3(16, 64), blk, FLASH_SMEM>>>(q, kT, v, o2, 0);
    sgemm_kernel<false, true, false><<<dim3(8, 32), blk>>>(o2, Wo2, nullptr, outEnc, t1, 4096, 1024, 1024);
    ln_part_kernel<<<256, 256>>>(t1);
    ln_final_kernel<<<1, 32>>>();
    ln_apply_kernel<<<4096, 256>>>(t1, ln2w, ln2b, n2);

    // ---- FFN (the (B,S,E)->(B,E,S) reshape is identity on memory) ----
    sgemm_kernel<true, false, true><<<dim3(16, 32), blk>>>(n2, W1, b1, nullptr, fc1, 4096, 2048, 1024);
    sgemm_kernel<true, true, false><<<dim3(8, 32), blk>>>(fc1, W2, b2, n2, t1, 4096, 1024, 2048);
    ln_part_kernel<<<256, 256>>>(t1);
    ln_final_kernel<<<1, 32>>>();
    ln_apply_kernel<<<4096, 256>>>(t1, ln3w, ln3b, out);
}

// round 3
// speedup vs baseline: 1.1943x; 1.1943x over previous
#include <cuda_runtime.h>
#include <math.h>
#include <stdint.h>

#define N_ELEM 4194304  // 4*1024*1024

// ---------------- scratch (device globals) ----------------------------------
__device__ float  g_q [N_ELEM];
__device__ float  g_kT[N_ELEM];
__device__ float  g_v [N_ELEM];
__device__ float  g_o2[N_ELEM];
__device__ float  g_t1[N_ELEM];
__device__ float  g_n1[N_ELEM];
__device__ float  g_n2[N_ELEM];
__device__ float  g_fc1[4096 * 2048];
__device__ double g_part[256][2];
__device__ float  g_stats[4][2];

// ---------------- tf32 helpers ----------------------------------------------
__device__ __forceinline__ unsigned f2tf32(float x) {
    unsigned y;
    asm("cvt.rna.tf32.f32 %0, %1;" : "=r"(y) : "f"(x));
    return y;
}
__device__ __forceinline__ void split_tf32(float x, unsigned& hi, unsigned& lo) {
    hi = f2tf32(x);
    lo = f2tf32(x - __uint_as_float(hi));
}
__device__ __forceinline__ void mma_tf32(float* c, const unsigned* a, const unsigned* b) {
    asm volatile(
        "mma.sync.aligned.m16n8k8.row.col.f32.tf32.tf32.f32 "
        "{%0,%1,%2,%3}, {%4,%5,%6,%7}, {%8,%9}, {%0,%1,%2,%3};\n"
        : "+f"(c[0]), "+f"(c[1]), "+f"(c[2]), "+f"(c[3])
        : "r"(a[0]), "r"(a[1]), "r"(a[2]), "r"(a[3]), "r"(b[0]), "r"(b[1]));
}

// ---------------- unified tensor-core GEMM ----------------------------------
// MODE -1: generic row-major B, row-major C (+bias/res/relu)
// MODE  0: proj B-gather W[h,e,d]; C scatter to [hb][s][d]
// MODE  1: proj B-gather;          C scatter to kT layout [hb][t][dcol]
template<int MODE, bool BIAS, bool RES, bool RELU>
__global__ __launch_bounds__(256)
void mma_gemm(const float* __restrict__ A, const float* __restrict__ B,
              const float* __restrict__ bias, const float* __restrict__ res,
              float* __restrict__ C, int M, int N, int K)
{
    __shared__ float As[128 * 36];   // stride 36: frag loads bank-conflict-free
    __shared__ float Bs[32 * 136];   // stride 136: ditto
    const int tid  = threadIdx.x;
    const int lane = tid & 31, wid = tid >> 5;
    const int g = lane >> 2, tig = lane & 3;
    const int wm = wid >> 2, wn = wid & 3;
    const int m0 = blockIdx.y << 7, n0 = blockIdx.x << 7;

    float acc[4][4][4];
#pragma unroll
    for (int mt = 0; mt < 4; mt++)
#pragma unroll
        for (int nt = 0; nt < 4; nt++)
#pragma unroll
            for (int c = 0; c < 4; c++) acc[mt][nt][c] = 0.f;

    const int aRow = tid >> 3, aCol = (tid & 7) << 2;   // A: 128x32, 4 rounds of 32 rows
    const int bRow = tid >> 5, bCol = (tid & 31) << 2;  // B: 32x128, 4 rounds of 8 rows

    float4 pa[4], pb[4];

    // prologue: preload k0 = 0
#pragma unroll
    for (int r = 0; r < 4; r++)
        pa[r] = *(const float4*)(A + (size_t)(m0 + aRow + r * 32) * K + aCol);
#pragma unroll
    for (int r = 0; r < 4; r++) {
        if constexpr (MODE < 0) {
            pb[r] = *(const float4*)(B + (size_t)(bRow + r * 8) * N + n0 + bCol);
        } else {
            const int n = n0 + bCol;
            pb[r] = *(const float4*)(B + ((size_t)(n >> 6) << 16)
                                       + ((size_t)(bRow + r * 8) << 6) + (n & 63));
        }
    }

    for (int k0 = 0;;) {
#pragma unroll
        for (int r = 0; r < 4; r++)
            *(float4*)&As[(aRow + r * 32) * 36 + aCol] = pa[r];
#pragma unroll
        for (int r = 0; r < 4; r++)
            *(float4*)&Bs[(bRow + r * 8) * 136 + bCol] = pb[r];
        __syncthreads();

        const int kn = k0 + 32;
        if (kn < K) {
#pragma unroll
            for (int r = 0; r < 4; r++)
                pa[r] = *(const float4*)(A + (size_t)(m0 + aRow + r * 32) * K + kn + aCol);
#pragma unroll
            for (int r = 0; r < 4; r++) {
                if constexpr (MODE < 0) {
                    pb[r] = *(const float4*)(B + (size_t)(kn + bRow + r * 8) * N + n0 + bCol);
                } else {
                    const int n = n0 + bCol;
                    pb[r] = *(const float4*)(B + ((size_t)(n >> 6) << 16)
                                               + ((size_t)(kn + bRow + r * 8) << 6) + (n & 63));
                }
            }
        }

#pragma unroll
        for (int kt = 0; kt < 4; kt++) {
            const int kk = kt << 3;
            unsigned ahi[4][4], alo[4][4], bhi[4][2], blo[4][2];
#pragma unroll
            for (int mt = 0; mt < 4; mt++) {
                const int mb = (wm << 6) + (mt << 4);
                float a0 = As[(mb + g) * 36 + kk + tig];
                float a1 = As[(mb + g + 8) * 36 + kk + tig];
                float a2 = As[(mb + g) * 36 + kk + tig + 4];
                float a3 = As[(mb + g + 8) * 36 + kk + tig + 4];
                split_tf32(a0, ahi[mt][0], alo[mt][0]);
                split_tf32(a1, ahi[mt][1], alo[mt][1]);
                split_tf32(a2, ahi[mt][2], alo[mt][2]);
                split_tf32(a3, ahi[mt][3], alo[mt][3]);
            }
#pragma unroll
            for (int nt = 0; nt < 4; nt++) {
                const int nb = (wn << 5) + (nt << 3);
                float b0 = Bs[(kk + tig) * 136 + nb + g];
                float b1 = Bs[(kk + tig + 4) * 136 + nb + g];
                split_tf32(b0, bhi[nt][0], blo[nt][0]);
                split_tf32(b1, bhi[nt][1], blo[nt][1]);
            }
#pragma unroll
            for (int mt = 0; mt < 4; mt++)
#pragma unroll
                for (int nt = 0; nt < 4; nt++) {
                    mma_tf32(acc[mt][nt], ahi[mt], bhi[nt]);
                    mma_tf32(acc[mt][nt], alo[mt], bhi[nt]);
                    mma_tf32(acc[mt][nt], ahi[mt], blo[nt]);
                }
        }
        k0 = kn;
        if (k0 >= K) break;
        __syncthreads();
    }

    // ---------------- epilogue ----------------
#pragma unroll
    for (int mt = 0; mt < 4; mt++) {
#pragma unroll
        for (int nt = 0; nt < 4; nt++) {
            const int m = m0 + (wm << 6) + (mt << 4) + g;
            const int n = n0 + (wn << 5) + (nt << 3) + (tig << 1);
            const float* c = acc[mt][nt];
            float2 v0 = make_float2(c[0], c[1]);   // row m,   cols n, n+1
            float2 v1 = make_float2(c[2], c[3]);   // row m+8, cols n, n+1

            if constexpr (MODE < 0) {
                if (BIAS) {
                    float2 bv = *(const float2*)(bias + n);
                    v0.x += bv.x; v0.y += bv.y; v1.x += bv.x; v1.y += bv.y;
                }
                if (RES) {
                    float2 r0 = *(const float2*)(res + (size_t)m * N + n);
                    float2 r1 = *(const float2*)(res + (size_t)(m + 8) * N + n);
                    v0.x += r0.x; v0.y += r0.y; v1.x += r1.x; v1.y += r1.y;
                }
                if (RELU) {
                    v0.x = fmaxf(v0.x, 0.f); v0.y = fmaxf(v0.y, 0.f);
                    v1.x = fmaxf(v1.x, 0.f); v1.y = fmaxf(v1.y, 0.f);
                }
                *(float2*)(C + (size_t)m * N + n) = v0;
                *(float2*)(C + (size_t)(m + 8) * N + n) = v1;
            } else if constexpr (MODE == 0) {
                const int b = m >> 10, s = m & 1023;
                const int h = n >> 6, d = n & 63;
                const size_t hb = (size_t)(h * 4 + b);
                *(float2*)(C + (((hb << 10) + s) << 6) + d) = v0;
                *(float2*)(C + (((hb << 10) + s + 8) << 6) + d) = v1;
            } else {
                const int b = m >> 10, s = m & 1023;
                const int h = n >> 6, d = n & 63;
                const size_t hb = (size_t)(h * 4 + b);
                const int t0a = ((s & 15) << 6) | d;
                const int t0b = (((s + 8) & 15) << 6) | d;
                C[((hb << 10) + t0a)     * 64 + (s >> 4)]       = c[0];
                C[((hb << 10) + t0a + 1) * 64 + (s >> 4)]       = c[1];
                C[((hb << 10) + t0b)     * 64 + ((s + 8) >> 4)] = c[2];
                C[((hb << 10) + t0b + 1) * 64 + ((s + 8) >> 4)] = c[3];
            }
        }
    }
}

// ---------------- fused flash attention (fp32) ------------------------------
__global__ __launch_bounds__(256)
void flash_kernel(const float* __restrict__ Q, const float* __restrict__ KT,
                  const float* __restrict__ V, float* __restrict__ O2, int causal)
{
    extern __shared__ float sm[];
    float* Qd = sm;
    float* KP = sm + 64 * 68;
    float* Vs = sm + 2 * 64 * 68;

    const int tid = threadIdx.x;
    const int tx = tid & 15, ty = tid >> 4;
    const int s0 = blockIdx.x << 6;
    const int hb = blockIdx.y;
    const size_t base = (size_t)hb << 16;

    const int lr = tid >> 2;
    const int ld4 = (tid & 3) << 4;

#pragma unroll
    for (int c = 0; c < 16; c += 4) {
        float4 qv = *(const float4*)(Q + base + ((size_t)(s0 + lr) << 6) + ld4 + c);
        Qd[(ld4 + c + 0) * 68 + lr] = qv.x;
        Qd[(ld4 + c + 1) * 68 + lr] = qv.y;
        Qd[(ld4 + c + 2) * 68 + lr] = qv.z;
        Qd[(ld4 + c + 3) * 68 + lr] = qv.w;
    }

    float o[4][4], m[4], l[4];
#pragma unroll
    for (int i = 0; i < 4; i++) {
        m[i] = -INFINITY; l[i] = 0.f;
#pragma unroll
        for (int j = 0; j < 4; j++) o[i][j] = 0.f;
    }

    const int ntiles = causal ? ((int)blockIdx.x + 1) : 16;
    for (int jt = 0; jt < ntiles; jt++) {
        const int t0 = jt << 6;
        __syncthreads();
#pragma unroll
        for (int c = 0; c < 16; c += 4) {
            float4 kv = *(const float4*)(KT + base + ((size_t)(t0 + lr) << 6) + ld4 + c);
            KP[(ld4 + c + 0) * 68 + lr] = kv.x;
            KP[(ld4 + c + 1) * 68 + lr] = kv.y;
            KP[(ld4 + c + 2) * 68 + lr] = kv.z;
            KP[(ld4 + c + 3) * 68 + lr] = kv.w;
            float4 vv = *(const float4*)(V + base + ((size_t)(t0 + lr) << 6) + ld4 + c);
            *(float4*)&Vs[lr * 68 + ld4 + c] = vv;
        }
        __syncthreads();

        float sc[4][4];
#pragma unroll
        for (int i = 0; i < 4; i++)
#pragma unroll
            for (int j = 0; j < 4; j++) sc[i][j] = 0.f;
#pragma unroll 16
        for (int d = 0; d < 64; d++) {
            float4 qv = *(const float4*)&Qd[d * 68 + (ty << 2)];
            float4 kv = *(const float4*)&KP[d * 68 + (tx << 2)];
            const float qa[4] = {qv.x, qv.y, qv.z, qv.w};
            const float ka[4] = {kv.x, kv.y, kv.z, kv.w};
#pragma unroll
            for (int i = 0; i < 4; i++)
#pragma unroll
                for (int j = 0; j < 4; j++)
                    sc[i][j] = fmaf(qa[i], ka[j], sc[i][j]);
        }
        __syncthreads();

        float p[4][4];
#pragma unroll
        for (int i = 0; i < 4; i++) {
            const int srow = s0 + (ty << 2) + i;
            float mx = -INFINITY;
#pragma unroll
            for (int j = 0; j < 4; j++) {
                float v = sc[i][j] * 0.125f;
                if (causal && (t0 + (tx << 2) + j > srow)) v = -INFINITY;
                sc[i][j] = v;
                mx = fmaxf(mx, v);
            }
            mx = fmaxf(mx, __shfl_xor_sync(0xffffffffu, mx, 1));
            mx = fmaxf(mx, __shfl_xor_sync(0xffffffffu, mx, 2));
            mx = fmaxf(mx, __shfl_xor_sync(0xffffffffu, mx, 4));
            mx = fmaxf(mx, __shfl_xor_sync(0xffffffffu, mx, 8));
            const float mnew = fmaxf(m[i], mx);
            const float corr = __expf(m[i] - mnew);
            m[i] = mnew;
            float rs = 0.f;
#pragma unroll
            for (int j = 0; j < 4; j++) {
                const float pe = __expf(sc[i][j] - mnew);
                p[i][j] = pe;
                rs += pe;
            }
            rs += __shfl_xor_sync(0xffffffffu, rs, 1);
            rs += __shfl_xor_sync(0xffffffffu, rs, 2);
            rs += __shfl_xor_sync(0xffffffffu, rs, 4);
            rs += __shfl_xor_sync(0xffffffffu, rs, 8);
            l[i] = l[i] * corr + rs;
#pragma unroll
            for (int j = 0; j < 4; j++) o[i][j] *= corr;
        }

#pragma unroll
        for (int j = 0; j < 4; j++) {
            float4 pv = make_float4(p[0][j], p[1][j], p[2][j], p[3][j]);
            *(float4*)&KP[((tx << 2) + j) * 68 + (ty << 2)] = pv;
        }
        __syncthreads();

#pragma unroll 16
        for (int t = 0; t < 64; t++) {
            float4 pf = *(const float4*)&KP[t * 68 + (ty << 2)];
            float4 vf = *(const float4*)&Vs[t * 68 + (tx << 2)];
            const float pa[4] = {pf.x, pf.y, pf.z, pf.w};
            const float va[4] = {vf.x, vf.y, vf.z, vf.w};
#pragma unroll
            for (int i = 0; i < 4; i++)
#pragma unroll
                for (int j = 0; j < 4; j++)
                    o[i][j] = fmaf(pa[i], va[j], o[i][j]);
        }
    }

    const int h = hb >> 2, b = hb & 3;
#pragma unroll
    for (int i = 0; i < 4; i++) {
        const int s = s0 + (ty << 2) + i;
        const float invl = 1.f / l[i];
        const size_t row = ((size_t)((h >> 2) * 1024 + (h & 3) * 256 + b * 64 + (s >> 4)) << 10)
                         + ((s & 15) << 6);
        float4 ov = make_float4(o[i][0] * invl, o[i][1] * invl, o[i][2] * invl, o[i][3] * invl);
        *(float4*)(O2 + row + (tx << 2)) = ov;
    }
}

// ---------------- LayerNorm over (S,E) slab per batch -----------------------
__global__ void ln_part_kernel(const float* __restrict__ X)
{
    __shared__ double sd[256];
    __shared__ double sq[256];
    const int tid = threadIdx.x;
    const float4* p = (const float4*)(X + ((size_t)blockIdx.x << 14));
    float s = 0.f, q = 0.f;
#pragma unroll
    for (int it = 0; it < 16; it++) {
        float4 v = p[it * 256 + tid];
        s += v.x + v.y + v.z + v.w;
        q += v.x * v.x + v.y * v.y + v.z * v.z + v.w * v.w;
    }
    sd[tid] = (double)s; sq[tid] = (double)q;
    __syncthreads();
    for (int off = 128; off > 0; off >>= 1) {
        if (tid < off) { sd[tid] += sd[tid + off]; sq[tid] += sq[tid + off]; }
        __syncthreads();
    }
    if (tid == 0) { g_part[blockIdx.x][0] = sd[0]; g_part[blockIdx.x][1] = sq[0]; }
}

__global__ void ln_final_kernel()
{
    const int b = threadIdx.x;
    if (b < 4) {
        double s = 0.0, q = 0.0;
        for (int i = 0; i < 64; i++) { s += g_part[b * 64 + i][0]; q += g_part[b * 64 + i][1]; }
        const double inv_n = 1.0 / 1048576.0;
        const double mean = s * inv_n;
        const double var = q * inv_n - mean * mean;
        g_stats[b][0] = (float)mean;
        g_stats[b][1] = (float)(1.0 / sqrt(var + 1e-5));
    }
}

__global__ void ln_apply_kernel(const float* __restrict__ X, const float* __restrict__ w,
                                const float* __restrict__ bb, float* __restrict__ Y)
{
    const size_t i = ((size_t)blockIdx.x * 256 + threadIdx.x) << 2;
    const int b = (int)(i >> 20);
    const float mean = g_stats[b][0], inv = g_stats[b][1];
    const size_t wi = i & 1048575;
    float4 x = *(const float4*)(X + i);
    float4 wv = *(const float4*)(w + wi);
    float4 bv = *(const float4*)(bb + wi);
    float4 y;
    y.x = (x.x - mean) * inv * wv.x + bv.x;
    y.y = (x.y - mean) * inv * wv.y + bv.y;
    y.z = (x.z - mean) * inv * wv.z + bv.z;
    y.w = (x.w - mean) * inv * wv.w + bv.w;
    *(float4*)(Y + i) = y;
}

// ---------------- driver ----------------------------------------------------
extern "C" void kernel_launch(void* const* d_in, const int* in_sizes, int n_in,
                              void* d_out, int out_size)
{
    const float* inputRes = (const float*)d_in[0];
    const float* outEnc   = (const float*)d_in[1];
    const float* Wq1 = (const float*)d_in[2];
    const float* Wk1 = (const float*)d_in[3];
    const float* Wv1 = (const float*)d_in[4];
    const float* Wo1 = (const float*)d_in[5];
    const float* Wq2 = (const float*)d_in[6];
    const float* Wk2 = (const float*)d_in[7];
    const float* Wv2 = (const float*)d_in[8];
    const float* Wo2 = (const float*)d_in[9];
    const float* ln1w = (const float*)d_in[10];
    const float* ln1b = (const float*)d_in[11];
    const float* ln2w = (const float*)d_in[12];
    const float* ln2b = (const float*)d_in[13];
    const float* ln3w = (const float*)d_in[14];
    const float* ln3b = (const float*)d_in[15];
    const float* W1 = (const float*)d_in[16];
    const float* b1 = (const float*)d_in[17];
    const float* W2 = (const float*)d_in[18];
    const float* b2 = (const float*)d_in[19];
    float* out = (float*)d_out;

    float *q, *kT, *v, *o2, *t1, *n1, *n2, *fc1;
    cudaGetSymbolAddress((void**)&q,   g_q);
    cudaGetSymbolAddress((void**)&kT,  g_kT);
    cudaGetSymbolAddress((void**)&v,   g_v);
    cudaGetSymbolAddress((void**)&o2,  g_o2);
    cudaGetSymbolAddress((void**)&t1,  g_t1);
    cudaGetSymbolAddress((void**)&n1,  g_n1);
    cudaGetSymbolAddress((void**)&n2,  g_n2);
    cudaGetSymbolAddress((void**)&fc1, g_fc1);

    const int FLASH_SMEM = 3 * 64 * 68 * 4;
    cudaFuncSetAttribute(flash_kernel, cudaFuncAttributeMaxDynamicSharedMemorySize, FLASH_SMEM);

    dim3 blk(256);
    dim3 g1024(8, 32);   // N=1024 tiles
    dim3 g2048(16, 32);  // N=2048 tiles

    // ---- MHA1 (self, causal) ----
    mma_gemm<0, false, false, false><<<g1024, blk>>>(outEnc, Wq1, nullptr, nullptr, q,  4096, 1024, 1024);
    mma_gemm<1, false, false, false><<<g1024, blk>>>(outEnc, Wk1, nullptr, nullptr, kT, 4096, 1024, 1024);
    mma_gemm<0, false, false, false><<<g1024, blk>>>(outEnc, Wv1, nullptr, nullptr, v,  4096, 1024, 1024);
    flash_kernel<<<dim3(16, 64), blk, FLASH_SMEM>>>(q, kT, v, o2, 1);
    mma_gemm<-1, false, true, false><<<g1024, blk>>>(o2, Wo1, nullptr, outEnc, t1, 4096, 1024, 1024);
    ln_part_kernel<<<256, 256>>>(t1);
    ln_final_kernel<<<1, 32>>>();
    ln_apply_kernel<<<4096, 256>>>(t1, ln1w, ln1b, n1);

    // ---- MHA2 (cross) ----
    mma_gemm<0, false, false, false><<<g1024, blk>>>(n1,       Wq2, nullptr, nullptr, q,  4096, 1024, 1024);
    mma_gemm<1, false, false, false><<<g1024, blk>>>(inputRes, Wk2, nullptr, nullptr, kT, 4096, 1024, 1024);
    mma_gemm<0, false, false, false><<<g1024, blk>>>(inputRes, Wv2, nullptr, nullptr, v,  4096, 1024, 1024);
    flash_kernel<<<dim3(16, 64), blk, FLASH_SMEM>>>(q, kT, v, o2, 0);
    mma_gemm<-1, false, true, false><<<g1024, blk>>>(o2, Wo2, nullptr, outEnc, t1, 4096, 1024, 1024);
    ln_part_kernel<<<256, 256>>>(t1);
    ln_final_kernel<<<1, 32>>>();
    ln_apply_kernel<<<4096, 256>>>(t1, ln2w, ln2b, n2);

    // ---- FFN ----
    mma_gemm<-1, true, false, true ><<<g2048, blk>>>(n2,  W1, b1, nullptr, fc1, 4096, 2048, 1024);
    mma_gemm<-1, true, true,  false><<<g1024, blk>>>(fc1, W2, b2, n2,      t1,  4096, 1024, 2048);
    ln_part_kernel<<<256, 256>>>(t1);
    ln_final_kernel<<<1, 32>>>();
    ln_apply_kernel<<<4096, 256>>>(t1, ln3w, ln3b, out);
}

// round 6
// speedup vs baseline: 1.2981x; 1.0870x over previous
#include <cuda_runtime.h>
#include <cuda_bf16.h>
#include <math.h>
#include <stdint.h>

#define N_ELEM 4194304  // 4*1024*1024

// ---------------- scratch (device globals) ----------------------------------
__device__ float  g_q [N_ELEM];
__device__ float  g_kT[N_ELEM];
__device__ float  g_v [N_ELEM];
__device__ float  g_o2[N_ELEM];
__device__ float  g_t1[N_ELEM];
__device__ float  g_n1[N_ELEM];
__device__ float  g_n2[N_ELEM];
__device__ float  g_fc1[4096 * 2048];
__device__ double g_part[256][2];
__device__ float  g_stats[4][2];
// split bf16 weight planes: per weight [3][N][K]
__device__ __nv_bfloat16 g_ws[37748736];  // 75.5 MB

#define OFF_WQ1 0
#define OFF_WK1 3145728
#define OFF_WV1 6291456
#define OFF_WO1 9437184
#define OFF_WQ2 12582912
#define OFF_WK2 15728640
#define OFF_WV2 18874368
#define OFF_WO2 22020096
#define OFF_W1  25165824
#define OFF_W2  31457280

// ---------------- mma.sync bf16 helper ---------------------------------------
__device__ __forceinline__ void mma_bf16(float* c, const unsigned* a, const unsigned* b) {
    asm volatile(
        "mma.sync.aligned.m16n8k16.row.col.f32.bf16.bf16.f32 "
        "{%0,%1,%2,%3}, {%4,%5,%6,%7}, {%8,%9}, {%0,%1,%2,%3};\n"
        : "+f"(c[0]), "+f"(c[1]), "+f"(c[2]), "+f"(c[3])
        : "r"(a[0]), "r"(a[1]), "r"(a[2]), "r"(a[3]), "r"(b[0]), "r"(b[1]));
}

// ---------------- weight transpose + 3-way bf16 split ------------------------
// out[p][n][k] = plane p of W_logical[k][n];  PROJ: W[h,e,d], n=(h<<6)|d, k=e
template<int PROJ>
__global__ __launch_bounds__(256)
void wsplit_kernel(const float* __restrict__ W, __nv_bfloat16* __restrict__ out,
                   int N, int K)
{
    __shared__ float t[64][65];
    const int tid = threadIdx.x;
    const int n0 = blockIdx.x << 6, k0 = blockIdx.y << 6;
#pragma unroll
    for (int r = 0; r < 4; r++) {
        const int flat = tid + (r << 8);
        const int kr = flat >> 4, nc = (flat & 15) << 2;
        const float* src;
        if (PROJ) src = W + ((size_t)((n0 + nc) >> 6) << 16) + ((size_t)(k0 + kr) << 6) + ((n0 + nc) & 63);
        else      src = W + (size_t)(k0 + kr) * N + n0 + nc;
        float4 v = *(const float4*)src;
        t[kr][nc] = v.x; t[kr][nc + 1] = v.y; t[kr][nc + 2] = v.z; t[kr][nc + 3] = v.w;
    }
    __syncthreads();
    const size_t ps = (size_t)N * K;
#pragma unroll
    for (int r = 0; r < 4; r++) {
        const int flat = tid + (r << 8);
        const int nr = flat >> 4, kc = (flat & 15) << 2;
        unsigned short u0[4], u1[4], u2[4];
#pragma unroll
        for (int j = 0; j < 4; j++) {
            float x = t[kc + j][nr];
            __nv_bfloat16 b0 = __float2bfloat16_rn(x);
            float r1 = x - __bfloat162float(b0);
            __nv_bfloat16 b1 = __float2bfloat16_rn(r1);
            float r2 = r1 - __bfloat162float(b1);
            __nv_bfloat16 b2 = __float2bfloat16_rn(r2);
            u0[j] = __bfloat16_as_ushort(b0);
            u1[j] = __bfloat16_as_ushort(b1);
            u2[j] = __bfloat16_as_ushort(b2);
        }
        const size_t dst = (size_t)(n0 + nr) * K + k0 + kc;
        *(uint2*)(out + dst)          = make_uint2(u0[0] | (u0[1] << 16), u0[2] | (u0[3] << 16));
        *(uint2*)(out + ps + dst)     = make_uint2(u1[0] | (u1[1] << 16), u1[2] | (u1[3] << 16));
        *(uint2*)(out + 2 * ps + dst) = make_uint2(u2[0] | (u2[1] << 16), u2[2] | (u2[3] << 16));
    }
}

// ---------------- bf16 plane-split tensor-core GEMM --------------------------
// C[128x128/block] = A[M,K] fp32 (split in-flight to NP bf16 planes)
//                  * Bp (pre-split bf16 planes [>=NP][N][K], K-major)
// MODE -1: generic row-major C (+bias/res/relu); MODE 0: proj scatter; MODE 1: kT scatter
// smem per plane tile: 128 rows x 40 bf16 (stride 40 => conflict-free frags)
template<int NP, int MODE, bool BIAS, bool RES, bool RELU>
__global__ __launch_bounds__(256)
void bf_gemm(const float* __restrict__ A, const __nv_bfloat16* __restrict__ Bp,
             const float* __restrict__ bias, const float* __restrict__ res,
             float* __restrict__ C, int N, int K)
{
    extern __shared__ __nv_bfloat16 smp[];   // [2*NP][128*40]
    __nv_bfloat16* Asm = smp;                 // NP planes
    __nv_bfloat16* Bsm = smp + NP * 5120;     // NP planes (5120 = 128*40)

    const int tid  = threadIdx.x;
    const int lane = tid & 31, wid = tid >> 5;
    const int g = lane >> 2, tig = lane & 3;
    const int wm = wid >> 2, wn = wid & 3;
    const int m0 = blockIdx.y << 7, n0 = blockIdx.x << 7;
    const size_t bstride = (size_t)N * K;

    float acc[4][4][4];
#pragma unroll
    for (int mt = 0; mt < 4; mt++)
#pragma unroll
        for (int nt = 0; nt < 4; nt++)
#pragma unroll
            for (int c = 0; c < 4; c++) acc[mt][nt][c] = 0.f;

    constexpr int NPASS = (NP == 3) ? 6 : 3;
    constexpr int PI[6] = {0, 1, 0, 1, 2, 0};
    constexpr int PJ[6] = {0, 0, 1, 1, 0, 2};

    float4 pa[4];
    uint4  pb[NP][2];

    // ---- prologue prefetch (k0 = 0) ----
    // A: 128 rows x 32 fp32 = 1024 float4 -> row=flat>>3, col=(flat&7)*4
#pragma unroll
    for (int r = 0; r < 4; r++) {
        const int flat = tid + (r << 8);
        const int row = flat >> 3, c4 = (flat & 7) << 2;
        pa[r] = *(const float4*)(A + (size_t)(m0 + row) * K + c4);
    }
    // B: 128 rows x 32 bf16 = 512 uint4 -> row=flat>>2, seg=(flat&3)*8
#pragma unroll
    for (int p = 0; p < NP; p++)
#pragma unroll
        for (int r = 0; r < 2; r++) {
            const int flat = tid + (r << 8);
            const int row = flat >> 2, cs = (flat & 3) << 3;
            pb[p][r] = *(const uint4*)(Bp + (size_t)p * bstride + (size_t)(n0 + row) * K + cs);
        }

    for (int k0 = 0;;) {
        // ---- store A (split to NP bf16 planes) ----
#pragma unroll
        for (int r = 0; r < 4; r++) {
            const int flat = tid + (r << 8);
            const int row = flat >> 3, c4 = (flat & 7) << 2;
            float x[4] = {pa[r].x, pa[r].y, pa[r].z, pa[r].w};
            unsigned short u0[4], u1[4], u2[4];
#pragma unroll
            for (int j = 0; j < 4; j++) {
                __nv_bfloat16 b0 = __float2bfloat16_rn(x[j]);
                float r1 = x[j] - __bfloat162float(b0);
                __nv_bfloat16 b1 = __float2bfloat16_rn(r1);
                u0[j] = __bfloat16_as_ushort(b0);
                u1[j] = __bfloat16_as_ushort(b1);
                if (NP == 3) {
                    float r2 = r1 - __bfloat162float(b1);
                    u2[j] = __bfloat16_as_ushort(__float2bfloat16_rn(r2));
                }
            }
            const int off = row * 40 + c4;
            *(uint2*)(Asm + off)        = make_uint2(u0[0] | (u0[1] << 16), u0[2] | (u0[3] << 16));
            *(uint2*)(Asm + 5120 + off) = make_uint2(u1[0] | (u1[1] << 16), u1[2] | (u1[3] << 16));
            if (NP == 3)
                *(uint2*)(Asm + 10240 + off) = make_uint2(u2[0] | (u2[1] << 16), u2[2] | (u2[3] << 16));
        }
        // ---- store B planes ----
#pragma unroll
        for (int p = 0; p < NP; p++)
#pragma unroll
            for (int r = 0; r < 2; r++) {
                const int flat = tid + (r << 8);
                const int row = flat >> 2, cs = (flat & 3) << 3;
                *(uint4*)(Bsm + p * 5120 + row * 40 + cs) = pb[p][r];
            }
        __syncthreads();

        // ---- prefetch next stage ----
        const int kn = k0 + 32;
        if (kn < K) {
#pragma unroll
            for (int r = 0; r < 4; r++) {
                const int flat = tid + (r << 8);
                const int row = flat >> 3, c4 = (flat & 7) << 2;
                pa[r] = *(const float4*)(A + (size_t)(m0 + row) * K + kn + c4);
            }
#pragma unroll
            for (int p = 0; p < NP; p++)
#pragma unroll
                for (int r = 0; r < 2; r++) {
                    const int flat = tid + (r << 8);
                    const int row = flat >> 2, cs = (flat & 3) << 3;
                    pb[p][r] = *(const uint4*)(Bp + (size_t)p * bstride
                                               + (size_t)(n0 + row) * K + kn + cs);
                }
        }

        // ---- compute: NPASS plane passes x 2 k16 sub-steps ----
#pragma unroll
        for (int pp = 0; pp < NPASS; pp++) {
            const __nv_bfloat16* Ap = Asm + PI[pp] * 5120;
            const __nv_bfloat16* Bq = Bsm + PJ[pp] * 5120;
#pragma unroll
            for (int kt = 0; kt < 2; kt++) {
                const int kb = kt << 4;
                unsigned af[4][4], bf_[4][2];
#pragma unroll
                for (int mt = 0; mt < 4; mt++) {
                    const int rb = (wm << 6) + (mt << 4);
                    af[mt][0] = *(const unsigned*)(Ap + (rb + g) * 40 + kb + (tig << 1));
                    af[mt][1] = *(const unsigned*)(Ap + (rb + g + 8) * 40 + kb + (tig << 1));
                    af[mt][2] = *(const unsigned*)(Ap + (rb + g) * 40 + kb + 8 + (tig << 1));
                    af[mt][3] = *(const unsigned*)(Ap + (rb + g + 8) * 40 + kb + 8 + (tig << 1));
                }
#pragma unroll
                for (int nt = 0; nt < 4; nt++) {
                    const int nb = (wn << 5) + (nt << 3);
                    bf_[nt][0] = *(const unsigned*)(Bq + (nb + g) * 40 + kb + (tig << 1));
                    bf_[nt][1] = *(const unsigned*)(Bq + (nb + g) * 40 + kb + 8 + (tig << 1));
                }
#pragma unroll
                for (int mt = 0; mt < 4; mt++)
#pragma unroll
                    for (int nt = 0; nt < 4; nt++)
                        mma_bf16(acc[mt][nt], af[mt], bf_[nt]);
            }
        }

        k0 = kn;
        if (k0 >= K) break;
        __syncthreads();
    }

    // ---------------- epilogue ----------------
#pragma unroll
    for (int mt = 0; mt < 4; mt++) {
#pragma unroll
        for (int nt = 0; nt < 4; nt++) {
            const int m = m0 + (wm << 6) + (mt << 4) + g;
            const int n = n0 + (wn << 5) + (nt << 3) + (tig << 1);
            const float* c = acc[mt][nt];
            float2 v0 = make_float2(c[0], c[1]);   // row m,   cols n, n+1
            float2 v1 = make_float2(c[2], c[3]);   // row m+8, cols n, n+1

            if constexpr (MODE < 0) {
                if (BIAS) {
                    float2 bv = *(const float2*)(bias + n);
                    v0.x += bv.x; v0.y += bv.y; v1.x += bv.x; v1.y += bv.y;
                }
                if (RES) {
                    float2 r0 = *(const float2*)(res + (size_t)m * N + n);
                    float2 r1 = *(const float2*)(res + (size_t)(m + 8) * N + n);
                    v0.x += r0.x; v0.y += r0.y; v1.x += r1.x; v1.y += r1.y;
                }
                if (RELU) {
                    v0.x = fmaxf(v0.x, 0.f); v0.y = fmaxf(v0.y, 0.f);
                    v1.x = fmaxf(v1.x, 0.f); v1.y = fmaxf(v1.y, 0.f);
                }
                *(float2*)(C + (size_t)m * N + n) = v0;
                *(float2*)(C + (size_t)(m + 8) * N + n) = v1;
            } else if constexpr (MODE == 0) {
                const int b = m >> 10, s = m & 1023;
                const int h = n >> 6, d = n & 63;
                const size_t hb = (size_t)(h * 4 + b);
                *(float2*)(C + (((hb << 10) + s) << 6) + d) = v0;
                *(float2*)(C + (((hb << 10) + s + 8) << 6) + d) = v1;
            } else {
                const int b = m >> 10, s = m & 1023;
                const int h = n >> 6, d = n & 63;
                const size_t hb = (size_t)(h * 4 + b);
                const int t0a = ((s & 15) << 6) | d;
                const int t0b = (((s + 8) & 15) << 6) | d;
                C[((hb << 10) + t0a)     * 64 + (s >> 4)]       = c[0];
                C[((hb << 10) + t0a + 1) * 64 + (s >> 4)]       = c[1];
                C[((hb << 10) + t0b)     * 64 + ((s + 8) >> 4)] = c[2];
                C[((hb << 10) + t0b + 1) * 64 + ((s + 8) >> 4)] = c[3];
            }
        }
    }
}

// ---------------- fused flash attention (fp32) -------------------------------
__global__ __launch_bounds__(256)
void flash_kernel(const float* __restrict__ Q, const float* __restrict__ KT,
                  const float* __restrict__ V, float* __restrict__ O2, int causal)
{
    extern __shared__ float sm[];
    float* Qd = sm;
    float* KP = sm + 64 * 68;
    float* Vs = sm + 2 * 64 * 68;

    const int tid = threadIdx.x;
    const int tx = tid & 15, ty = tid >> 4;
    const int s0 = blockIdx.x << 6;
    const int hb = blockIdx.y;
    const size_t base = (size_t)hb << 16;
    const int lr = tid >> 2;
    const int ld4 = (tid & 3) << 4;

#pragma unroll
    for (int c = 0; c < 16; c += 4) {
        float4 qv = *(const float4*)(Q + base + ((size_t)(s0 + lr) << 6) + ld4 + c);
        Qd[(ld4 + c + 0) * 68 + lr] = qv.x;
        Qd[(ld4 + c + 1) * 68 + lr] = qv.y;
        Qd[(ld4 + c + 2) * 68 + lr] = qv.z;
        Qd[(ld4 + c + 3) * 68 + lr] = qv.w;
    }

    float o[4][4], m[4], l[4];
#pragma unroll
    for (int i = 0; i < 4; i++) {
        m[i] = -INFINITY; l[i] = 0.f;
#pragma unroll
        for (int j = 0; j < 4; j++) o[i][j] = 0.f;
    }

    const int ntiles = causal ? ((int)blockIdx.x + 1) : 16;
    for (int jt = 0; jt < ntiles; jt++) {
        const int t0 = jt << 6;
        __syncthreads();
#pragma unroll
        for (int c = 0; c < 16; c += 4) {
            float4 kv = *(const float4*)(KT + base + ((size_t)(t0 + lr) << 6) + ld4 + c);
            KP[(ld4 + c + 0) * 68 + lr] = kv.x;
            KP[(ld4 + c + 1) * 68 + lr] = kv.y;
            KP[(ld4 + c + 2) * 68 + lr] = kv.z;
            KP[(ld4 + c + 3) * 68 + lr] = kv.w;
            float4 vv = *(const float4*)(V + base + ((size_t)(t0 + lr) << 6) + ld4 + c);
            *(float4*)&Vs[lr * 68 + ld4 + c] = vv;
        }
        __syncthreads();

        float sc[4][4];
#pragma unroll
        for (int i = 0; i < 4; i++)
#pragma unroll
            for (int j = 0; j < 4; j++) sc[i][j] = 0.f;
#pragma unroll 16
        for (int d = 0; d < 64; d++) {
            float4 qv = *(const float4*)&Qd[d * 68 + (ty << 2)];
            float4 kv = *(const float4*)&KP[d * 68 + (tx << 2)];
            const float qa[4] = {qv.x, qv.y, qv.z, qv.w};
            const float ka[4] = {kv.x, kv.y, kv.z, kv.w};
#pragma unroll
            for (int i = 0; i < 4; i++)
#pragma unroll
                for (int j = 0; j < 4; j++)
                    sc[i][j] = fmaf(qa[i], ka[j], sc[i][j]);
        }
        __syncthreads();

        float p[4][4];
#pragma unroll
        for (int i = 0; i < 4; i++) {
            const int srow = s0 + (ty << 2) + i;
            float mx = -INFINITY;
#pragma unroll
            for (int j = 0; j < 4; j++) {
                float v = sc[i][j] * 0.125f;
                if (causal && (t0 + (tx << 2) + j > srow)) v = -INFINITY;
                sc[i][j] = v;
                mx = fmaxf(mx, v);
            }
            mx = fmaxf(mx, __shfl_xor_sync(0xffffffffu, mx, 1));
            mx = fmaxf(mx, __shfl_xor_sync(0xffffffffu, mx, 2));
            mx = fmaxf(mx, __shfl_xor_sync(0xffffffffu, mx, 4));
            mx = fmaxf(mx, __shfl_xor_sync(0xffffffffu, mx, 8));
            const float mnew = fmaxf(m[i], mx);
            const float corr = __expf(m[i] - mnew);
            m[i] = mnew;
            float rs = 0.f;
#pragma unroll
            for (int j = 0; j < 4; j++) {
                const float pe = __expf(sc[i][j] - mnew);
                p[i][j] = pe;
                rs += pe;
            }
            rs += __shfl_xor_sync(0xffffffffu, rs, 1);
            rs += __shfl_xor_sync(0xffffffffu, rs, 2);
            rs += __shfl_xor_sync(0xffffffffu, rs, 4);
            rs += __shfl_xor_sync(0xffffffffu, rs, 8);
            l[i] = l[i] * corr + rs;
#pragma unroll
            for (int j = 0; j < 4; j++) o[i][j] *= corr;
        }

#pragma unroll
        for (int j = 0; j < 4; j++) {
            float4 pv = make_float4(p[0][j], p[1][j], p[2][j], p[3][j]);
            *(float4*)&KP[((tx << 2) + j) * 68 + (ty << 2)] = pv;
        }
        __syncthreads();

#pragma unroll 16
        for (int t = 0; t < 64; t++) {
            float4 pf = *(const float4*)&KP[t * 68 + (ty << 2)];
            float4 vf = *(const float4*)&Vs[t * 68 + (tx << 2)];
            const float pa[4] = {pf.x, pf.y, pf.z, pf.w};
            const float va[4] = {vf.x, vf.y, vf.z, vf.w};
#pragma unroll
            for (int i = 0; i < 4; i++)
#pragma unroll
                for (int j = 0; j < 4; j++)
                    o[i][j] = fmaf(pa[i], va[j], o[i][j]);
        }
    }

    const int h = hb >> 2, b = hb & 3;
#pragma unroll
    for (int i = 0; i < 4; i++) {
        const int s = s0 + (ty << 2) + i;
        const float invl = 1.f / l[i];
        const size_t row = ((size_t)((h >> 2) * 1024 + (h & 3) * 256 + b * 64 + (s >> 4)) << 10)
                         + ((s & 15) << 6);
        float4 ov = make_float4(o[i][0] * invl, o[i][1] * invl, o[i][2] * invl, o[i][3] * invl);
        *(float4*)(O2 + row + (tx << 2)) = ov;
    }
}

// ---------------- LayerNorm over (S,E) slab per batch ------------------------
__global__ void ln_part_kernel(const float* __restrict__ X)
{
    __shared__ double sd[256];
    __shared__ double sq[256];
    const int tid = threadIdx.x;
    const float4* p = (const float4*)(X + ((size_t)blockIdx.x << 14));
    float s = 0.f, q = 0.f;
#pragma unroll
    for (int it = 0; it < 16; it++) {
        float4 v = p[it * 256 + tid];
        s += v.x + v.y + v.z + v.w;
        q += v.x * v.x + v.y * v.y + v.z * v.z + v.w * v.w;
    }
    sd[tid] = (double)s; sq[tid] = (double)q;
    __syncthreads();
    for (int off = 128; off > 0; off >>= 1) {
        if (tid < off) { sd[tid] += sd[tid + off]; sq[tid] += sq[tid + off]; }
        __syncthreads();
    }
    if (tid == 0) { g_part[blockIdx.x][0] = sd[0]; g_part[blockIdx.x][1] = sq[0]; }
}

__global__ void ln_final_kernel()
{
    const int b = threadIdx.x;
    if (b < 4) {
        double s = 0.0, q = 0.0;
        for (int i = 0; i < 64; i++) { s += g_part[b * 64 + i][0]; q += g_part[b * 64 + i][1]; }
        const double inv_n = 1.0 / 1048576.0;
        const double mean = s * inv_n;
        const double var = q * inv_n - mean * mean;
        g_stats[b][0] = (float)mean;
        g_stats[b][1] = (float)(1.0 / sqrt(var + 1e-5));
    }
}

__global__ void ln_apply_kernel(const float* __restrict__ X, const float* __restrict__ w,
                                const float* __restrict__ bb, float* __restrict__ Y)
{
    const size_t i = ((size_t)blockIdx.x * 256 + threadIdx.x) << 2;
    const int b = (int)(i >> 20);
    const float mean = g_stats[b][0], inv = g_stats[b][1];
    const size_t wi = i & 1048575;
    float4 x = *(const float4*)(X + i);
    float4 wv = *(const float4*)(w + wi);
    float4 bv = *(const float4*)(bb + wi);
    float4 y;
    y.x = (x.x - mean) * inv * wv.x + bv.x;
    y.y = (x.y - mean) * inv * wv.y + bv.y;
    y.z = (x.z - mean) * inv * wv.z + bv.z;
    y.w = (x.w - mean) * inv * wv.w + bv.w;
    *(float4*)(Y + i) = y;
}

// ---------------- driver -----------------------------------------------------
extern "C" void kernel_launch(void* const* d_in, const int* in_sizes, int n_in,
                              void* d_out, int out_size)
{
    const float* inputRes = (const float*)d_in[0];
    const float* outEnc   = (const float*)d_in[1];
    const float* Wq1 = (const float*)d_in[2];
    const float* Wk1 = (const float*)d_in[3];
    const float* Wv1 = (const float*)d_in[4];
    const float* Wo1 = (const float*)d_in[5];
    const float* Wq2 = (const float*)d_in[6];
    const float* Wk2 = (const float*)d_in[7];
    const float* Wv2 = (const float*)d_in[8];
    const float* Wo2 = (const float*)d_in[9];
    const float* ln1w = (const float*)d_in[10];
    const float* ln1b = (const float*)d_in[11];
    const float* ln2w = (const float*)d_in[12];
    const float* ln2b = (const float*)d_in[13];
    const float* ln3w = (const float*)d_in[14];
    const float* ln3b = (const float*)d_in[15];
    const float* W1 = (const float*)d_in[16];
    const float* b1 = (const float*)d_in[17];
    const float* W2 = (const float*)d_in[18];
    const float* b2 = (const float*)d_in[19];
    float* out = (float*)d_out;

    float *q, *kT, *v, *o2, *t1, *n1, *n2, *fc1;
    __nv_bfloat16* ws;
    cudaGetSymbolAddress((void**)&q,   g_q);
    cudaGetSymbolAddress((void**)&kT,  g_kT);
    cudaGetSymbolAddress((void**)&v,   g_v);
    cudaGetSymbolAddress((void**)&o2,  g_o2);
    cudaGetSymbolAddress((void**)&t1,  g_t1);
    cudaGetSymbolAddress((void**)&n1,  g_n1);
    cudaGetSymbolAddress((void**)&n2,  g_n2);
    cudaGetSymbolAddress((void**)&fc1, g_fc1);
    cudaGetSymbolAddress((void**)&ws,  g_ws);

    const int FLASH_SMEM = 3 * 64 * 68 * 4;
    cudaFuncSetAttribute(flash_kernel, cudaFuncAttributeMaxDynamicSharedMemorySize, FLASH_SMEM);

    const int SM2 = 2 * 2 * 5120 * 2;  // 40960 B
    const int SM3 = 2 * 3 * 5120 * 2;  // 61440 B
    cudaFuncSetAttribute(bf_gemm<3, 0, false, false, false>, cudaFuncAttributeMaxDynamicSharedMemorySize, SM3);
    cudaFuncSetAttribute(bf_gemm<3, 1, false, false, false>, cudaFuncAttributeMaxDynamicSharedMemorySize, SM3);
    cudaFuncSetAttribute(bf_gemm<2, 0, false, false, false>, cudaFuncAttributeMaxDynamicSharedMemorySize, SM2);
    cudaFuncSetAttribute(bf_gemm<2, -1, false, true, false>, cudaFuncAttributeMaxDynamicSharedMemorySize, SM2);
    cudaFuncSetAttribute(bf_gemm<2, -1, true, false, true >, cudaFuncAttributeMaxDynamicSharedMemorySize, SM2);
    cudaFuncSetAttribute(bf_gemm<2, -1, true, true,  false>, cudaFuncAttributeMaxDynamicSharedMemorySize, SM2);

    dim3 blk(256);

    // ---- pre-split weights into transposed bf16 planes ----
    wsplit_kernel<1><<<dim3(16, 16), blk>>>(Wq1, ws + OFF_WQ1, 1024, 1024);
    wsplit_kernel<1><<<dim3(16, 16), blk>>>(Wk1, ws + OFF_WK1, 1024, 1024);
    wsplit_kernel<1><<<dim3(16, 16), blk>>>(Wv1, ws + OFF_WV1, 1024, 1024);
    wsplit_kernel<0><<<dim3(16, 16), blk>>>(Wo1, ws + OFF_WO1, 1024, 1024);
    wsplit_kernel<1><<<dim3(16, 16), blk>>>(Wq2, ws + OFF_WQ2, 1024, 1024);
    wsplit_kernel<1><<<dim3(16, 16), blk>>>(Wk2, ws + OFF_WK2, 1024, 1024);
    wsplit_kernel<1><<<dim3(16, 16), blk>>>(Wv2, ws + OFF_WV2, 1024, 1024);
    wsplit_kernel<0><<<dim3(16, 16), blk>>>(Wo2, ws + OFF_WO2, 1024, 1024);
    wsplit_kernel<0><<<dim3(32, 16), blk>>>(W1,  ws + OFF_W1,  2048, 1024);
    wsplit_kernel<0><<<dim3(16, 32), blk>>>(W2,  ws + OFF_W2,  1024, 2048);

    dim3 g1024(8, 32), g2048(16, 32);

    // ---- MHA1 (self, causal) ----
    bf_gemm<3, 0, false, false, false><<<g1024, blk, SM3>>>(outEnc, ws + OFF_WQ1, nullptr, nullptr, q,  1024, 1024);
    bf_gemm<3, 1, false, false, false><<<g1024, blk, SM3>>>(outEnc, ws + OFF_WK1, nullptr, nullptr, kT, 1024, 1024);
    bf_gemm<2, 0, false, false, false><<<g1024, blk, SM2>>>(outEnc, ws + OFF_WV1, nullptr, nullptr, v,  1024, 1024);
    flash_kernel<<<dim3(16, 64), blk, FLASH_SMEM>>>(q, kT, v, o2, 1);
    bf_gemm<2, -1, false, true, false><<<g1024, blk, SM2>>>(o2, ws + OFF_WO1, nullptr, outEnc, t1, 1024, 1024);
    ln_part_kernel<<<256, blk>>>(t1);
    ln_final_kernel<<<1, 32>>>();
    ln_apply_kernel<<<4096, blk>>>(t1, ln1w, ln1b, n1);

    // ---- MHA2 (cross) ----
    bf_gemm<3, 0, false, false, false><<<g1024, blk, SM3>>>(n1,       ws + OFF_WQ2, nullptr, nullptr, q,  1024, 1024);
    bf_gemm<3, 1, false, false, false><<<g1024, blk, SM3>>>(inputRes, ws + OFF_WK2, nullptr, nullptr, kT, 1024, 1024);
    bf_gemm<2, 0, false, false, false><<<g1024, blk, SM2>>>(inputRes, ws + OFF_WV2, nullptr, nullptr, v,  1024, 1024);
    flash_kernel<<<dim3(16, 64), blk, FLASH_SMEM>>>(q, kT, v, o2, 0);
    bf_gemm<2, -1, false, true, false><<<g1024, blk, SM2>>>(o2, ws + OFF_WO2, nullptr, outEnc, t1, 1024, 1024);
    ln_part_kernel<<<256, blk>>>(t1);
    ln_final_kernel<<<1, 32>>>();
    ln_apply_kernel<<<4096, blk>>>(t1, ln2w, ln2b, n2);

    // ---- FFN ----
    bf_gemm<2, -1, true, false, true ><<<g2048, blk, SM2>>>(n2,  ws + OFF_W1, b1, nullptr, fc1, 2048, 1024);
    bf_gemm<2, -1, true, true,  false><<<g1024, blk, SM2>>>(fc1, ws + OFF_W2, b2, n2,      t1,  1024, 2048);
    ln_part_kernel<<<256, blk>>>(t1);
    ln_final_kernel<<<1, 32>>>();
    ln_apply_kernel<<<4096, blk>>>(t1, ln3w, ln3b, out);
}

// round 7
// speedup vs baseline: 1.4590x; 1.1239x over previous
#include <cuda_runtime.h>
#include <cuda_fp16.h>
#include <math.h>
#include <stdint.h>

#define N_ELEM 4194304  // 4*1024*1024

// ---------------- scratch (device globals) ----------------------------------
__device__ float  g_q [N_ELEM];
__device__ float  g_kT[N_ELEM];
__device__ float  g_v [N_ELEM];
__device__ float  g_o2[N_ELEM];
__device__ float  g_t1[N_ELEM];
__device__ float  g_n1[N_ELEM];
__device__ float  g_n2[N_ELEM];
__device__ float  g_fc1[4096 * 2048];
__device__ double g_part[256][2];
__device__ float  g_stats[4][2];
// split fp16 weight planes: per weight [2][N][K]
__device__ __half g_ws[25165824];  // 48 MB

#define OFF_WQ1 0
#define OFF_WK1 2097152
#define OFF_WV1 4194304
#define OFF_WO1 6291456
#define OFF_WQ2 8388608
#define OFF_WK2 10485760
#define OFF_WV2 12582912
#define OFF_WO2 14680064
#define OFF_W1  16777216
#define OFF_W2  20971520

// ---------------- mma.sync fp16 helper ---------------------------------------
__device__ __forceinline__ void mma_f16(float* c, const unsigned* a, const unsigned* b) {
    asm volatile(
        "mma.sync.aligned.m16n8k16.row.col.f32.f16.f16.f32 "
        "{%0,%1,%2,%3}, {%4,%5,%6,%7}, {%8,%9}, {%0,%1,%2,%3};\n"
        : "+f"(c[0]), "+f"(c[1]), "+f"(c[2]), "+f"(c[3])
        : "r"(a[0]), "r"(a[1]), "r"(a[2]), "r"(a[3]), "r"(b[0]), "r"(b[1]));
}

// ---------------- weight transpose + 2-way fp16 split ------------------------
// out[p][n][k] = plane p of W_logical[k][n];  PROJ: W[h,e,d], n=(h<<6)|d, k=e
template<int PROJ>
__global__ __launch_bounds__(256)
void wsplit_kernel(const float* __restrict__ W, __half* __restrict__ out,
                   int N, int K)
{
    __shared__ float t[64][65];
    const int tid = threadIdx.x;
    const int n0 = blockIdx.x << 6, k0 = blockIdx.y << 6;
#pragma unroll
    for (int r = 0; r < 4; r++) {
        const int flat = tid + (r << 8);
        const int kr = flat >> 4, nc = (flat & 15) << 2;
        const float* src;
        if (PROJ) src = W + ((size_t)((n0 + nc) >> 6) << 16) + ((size_t)(k0 + kr) << 6) + ((n0 + nc) & 63);
        else      src = W + (size_t)(k0 + kr) * N + n0 + nc;
        float4 v = *(const float4*)src;
        t[kr][nc] = v.x; t[kr][nc + 1] = v.y; t[kr][nc + 2] = v.z; t[kr][nc + 3] = v.w;
    }
    __syncthreads();
    const size_t ps = (size_t)N * K;
#pragma unroll
    for (int r = 0; r < 4; r++) {
        const int flat = tid + (r << 8);
        const int nr = flat >> 4, kc = (flat & 15) << 2;
        unsigned short u0[4], u1[4];
#pragma unroll
        for (int j = 0; j < 4; j++) {
            float x = t[kc + j][nr];
            __half h0 = __float2half_rn(x);
            float r1 = x - __half2float(h0);
            __half h1 = __float2half_rn(r1);
            u0[j] = __half_as_ushort(h0);
            u1[j] = __half_as_ushort(h1);
        }
        const size_t dst = (size_t)(n0 + nr) * K + k0 + kc;
        *(uint2*)(out + dst)      = make_uint2(u0[0] | (u0[1] << 16), u0[2] | (u0[3] << 16));
        *(uint2*)(out + ps + dst) = make_uint2(u1[0] | (u1[1] << 16), u1[2] | (u1[3] << 16));
    }
}

// ---------------- fp16 2-plane tensor-core GEMM ------------------------------
// C[128x128/block] = A[M,K] fp32 (split in-flight to 2 fp16 planes)
//                  * Bp (pre-split fp16 planes [2][N][K], K-major)
// passes: hi*hi + lo*hi + hi*lo  (error ~2^-22 per product)
// MODE -1: generic row-major C (+bias/res/relu); MODE 0: proj scatter; MODE 1: kT scatter
// smem per plane tile: 128 rows x 40 halves (stride 40 => conflict-free frags)
template<int MODE, bool BIAS, bool RES, bool RELU>
__global__ __launch_bounds__(256)
void hf_gemm(const float* __restrict__ A, const __half* __restrict__ Bp,
             const float* __restrict__ bias, const float* __restrict__ res,
             float* __restrict__ C, int N, int K)
{
    extern __shared__ __half smp[];          // [4][128*40]
    __half* Asm = smp;                        // 2 planes
    __half* Bsm = smp + 2 * 5120;             // 2 planes (5120 = 128*40)

    const int tid  = threadIdx.x;
    const int lane = tid & 31, wid = tid >> 5;
    const int g = lane >> 2, tig = lane & 3;
    const int wm = wid >> 2, wn = wid & 3;
    const int m0 = blockIdx.y << 7, n0 = blockIdx.x << 7;
    const size_t bstride = (size_t)N * K;

    float acc[4][4][4];
#pragma unroll
    for (int mt = 0; mt < 4; mt++)
#pragma unroll
        for (int nt = 0; nt < 4; nt++)
#pragma unroll
            for (int c = 0; c < 4; c++) acc[mt][nt][c] = 0.f;

    constexpr int PI[3] = {0, 1, 0};
    constexpr int PJ[3] = {0, 0, 1};

    float4 pa[4];
    uint4  pb[2][2];

    // ---- prologue prefetch (k0 = 0) ----
    // A: 128 rows x 32 fp32 = 1024 float4 -> row=flat>>3, col=(flat&7)*4
#pragma unroll
    for (int r = 0; r < 4; r++) {
        const int flat = tid + (r << 8);
        const int row = flat >> 3, c4 = (flat & 7) << 2;
        pa[r] = *(const float4*)(A + (size_t)(m0 + row) * K + c4);
    }
    // B: 128 rows x 32 fp16 = 512 uint4 -> row=flat>>2, seg=(flat&3)*8
#pragma unroll
    for (int p = 0; p < 2; p++)
#pragma unroll
        for (int r = 0; r < 2; r++) {
            const int flat = tid + (r << 8);
            const int row = flat >> 2, cs = (flat & 3) << 3;
            pb[p][r] = *(const uint4*)(Bp + (size_t)p * bstride + (size_t)(n0 + row) * K + cs);
        }

    for (int k0 = 0;;) {
        // ---- store A (split to 2 fp16 planes) ----
#pragma unroll
        for (int r = 0; r < 4; r++) {
            const int flat = tid + (r << 8);
            const int row = flat >> 3, c4 = (flat & 7) << 2;
            float x[4] = {pa[r].x, pa[r].y, pa[r].z, pa[r].w};
            unsigned short u0[4], u1[4];
#pragma unroll
            for (int j = 0; j < 4; j++) {
                __half h0 = __float2half_rn(x[j]);
                float r1 = x[j] - __half2float(h0);
                __half h1 = __float2half_rn(r1);
                u0[j] = __half_as_ushort(h0);
                u1[j] = __half_as_ushort(h1);
            }
            const int off = row * 40 + c4;
            *(uint2*)(Asm + off)        = make_uint2(u0[0] | (u0[1] << 16), u0[2] | (u0[3] << 16));
            *(uint2*)(Asm + 5120 + off) = make_uint2(u1[0] | (u1[1] << 16), u1[2] | (u1[3] << 16));
        }
        // ---- store B planes ----
#pragma unroll
        for (int p = 0; p < 2; p++)
#pragma unroll
            for (int r = 0; r < 2; r++) {
                const int flat = tid + (r << 8);
                const int row = flat >> 2, cs = (flat & 3) << 3;
                *(uint4*)(Bsm + p * 5120 + row * 40 + cs) = pb[p][r];
            }
        __syncthreads();

        // ---- prefetch next stage ----
        const int kn = k0 + 32;
        if (kn < K) {
#pragma unroll
            for (int r = 0; r < 4; r++) {
                const int flat = tid + (r << 8);
                const int row = flat >> 3, c4 = (flat & 7) << 2;
                pa[r] = *(const float4*)(A + (size_t)(m0 + row) * K + kn + c4);
            }
#pragma unroll
            for (int p = 0; p < 2; p++)
#pragma unroll
                for (int r = 0; r < 2; r++) {
                    const int flat = tid + (r << 8);
                    const int row = flat >> 2, cs = (flat & 3) << 3;
                    pb[p][r] = *(const uint4*)(Bp + (size_t)p * bstride
                                               + (size_t)(n0 + row) * K + kn + cs);
                }
        }

        // ---- compute: 3 plane passes x 2 k16 sub-steps ----
#pragma unroll
        for (int pp = 0; pp < 3; pp++) {
            const __half* Ap = Asm + PI[pp] * 5120;
            const __half* Bq = Bsm + PJ[pp] * 5120;
#pragma unroll
            for (int kt = 0; kt < 2; kt++) {
                const int kb = kt << 4;
                unsigned af[4][4], bf_[4][2];
#pragma unroll
                for (int mt = 0; mt < 4; mt++) {
                    const int rb = (wm << 6) + (mt << 4);
                    af[mt][0] = *(const unsigned*)(Ap + (rb + g) * 40 + kb + (tig << 1));
                    af[mt][1] = *(const unsigned*)(Ap + (rb + g + 8) * 40 + kb + (tig << 1));
                    af[mt][2] = *(const unsigned*)(Ap + (rb + g) * 40 + kb + 8 + (tig << 1));
                    af[mt][3] = *(const unsigned*)(Ap + (rb + g + 8) * 40 + kb + 8 + (tig << 1));
                }
#pragma unroll
                for (int nt = 0; nt < 4; nt++) {
                    const int nb = (wn << 5) + (nt << 3);
                    bf_[nt][0] = *(const unsigned*)(Bq + (nb + g) * 40 + kb + (tig << 1));
                    bf_[nt][1] = *(const unsigned*)(Bq + (nb + g) * 40 + kb + 8 + (tig << 1));
                }
#pragma unroll
                for (int mt = 0; mt < 4; mt++)
#pragma unroll
                    for (int nt = 0; nt < 4; nt++)
                        mma_f16(acc[mt][nt], af[mt], bf_[nt]);
            }
        }

        k0 = kn;
        if (k0 >= K) break;
        __syncthreads();
    }

    // ---------------- epilogue ----------------
#pragma unroll
    for (int mt = 0; mt < 4; mt++) {
#pragma unroll
        for (int nt = 0; nt < 4; nt++) {
            const int m = m0 + (wm << 6) + (mt << 4) + g;
            const int n = n0 + (wn << 5) + (nt << 3) + (tig << 1);
            const float* c = acc[mt][nt];
            float2 v0 = make_float2(c[0], c[1]);   // row m,   cols n, n+1
            float2 v1 = make_float2(c[2], c[3]);   // row m+8, cols n, n+1

            if constexpr (MODE < 0) {
                if (BIAS) {
                    float2 bv = *(const float2*)(bias + n);
                    v0.x += bv.x; v0.y += bv.y; v1.x += bv.x; v1.y += bv.y;
                }
                if (RES) {
                    float2 r0 = *(const float2*)(res + (size_t)m * N + n);
                    float2 r1 = *(const float2*)(res + (size_t)(m + 8) * N + n);
                    v0.x += r0.x; v0.y += r0.y; v1.x += r1.x; v1.y += r1.y;
                }
                if (RELU) {
                    v0.x = fmaxf(v0.x, 0.f); v0.y = fmaxf(v0.y, 0.f);
                    v1.x = fmaxf(v1.x, 0.f); v1.y = fmaxf(v1.y, 0.f);
                }
                *(float2*)(C + (size_t)m * N + n) = v0;
                *(float2*)(C + (size_t)(m + 8) * N + n) = v1;
            } else if constexpr (MODE == 0) {
                const int b = m >> 10, s = m & 1023;
                const int h = n >> 6, d = n & 63;
                const size_t hb = (size_t)(h * 4 + b);
                *(float2*)(C + (((hb << 10) + s) << 6) + d) = v0;
                *(float2*)(C + (((hb << 10) + s + 8) << 6) + d) = v1;
            } else {
                const int b = m >> 10, s = m & 1023;
                const int h = n >> 6, d = n & 63;
                const size_t hb = (size_t)(h * 4 + b);
                const int t0a = ((s & 15) << 6) | d;
                const int t0b = (((s + 8) & 15) << 6) | d;
                C[((hb << 10) + t0a)     * 64 + (s >> 4)]       = c[0];
                C[((hb << 10) + t0a + 1) * 64 + (s >> 4)]       = c[1];
                C[((hb << 10) + t0b)     * 64 + ((s + 8) >> 4)] = c[2];
                C[((hb << 10) + t0b + 1) * 64 + ((s + 8) >> 4)] = c[3];
            }
        }
    }
}

// ---------------- fused flash attention (fp32) -------------------------------
__global__ __launch_bounds__(256)
void flash_kernel(const float* __restrict__ Q, const float* __restrict__ KT,
                  const float* __restrict__ V, float* __restrict__ O2, int causal)
{
    extern __shared__ float sm[];
    float* Qd = sm;
    float* KP = sm + 64 * 68;
    float* Vs = sm + 2 * 64 * 68;

    const int tid = threadIdx.x;
    const int tx = tid & 15, ty = tid >> 4;
    const int s0 = blockIdx.x << 6;
    const int hb = blockIdx.y;
    const size_t base = (size_t)hb << 16;
    const int lr = tid >> 2;
    const int ld4 = (tid & 3) << 4;

#pragma unroll
    for (int c = 0; c < 16; c += 4) {
        float4 qv = *(const float4*)(Q + base + ((size_t)(s0 + lr) << 6) + ld4 + c);
        Qd[(ld4 + c + 0) * 68 + lr] = qv.x;
        Qd[(ld4 + c + 1) * 68 + lr] = qv.y;
        Qd[(ld4 + c + 2) * 68 + lr] = qv.z;
        Qd[(ld4 + c + 3) * 68 + lr] = qv.w;
    }

    float o[4][4], m[4], l[4];
#pragma unroll
    for (int i = 0; i < 4; i++) {
        m[i] = -INFINITY; l[i] = 0.f;
#pragma unroll
        for (int j = 0; j < 4; j++) o[i][j] = 0.f;
    }

    const int ntiles = causal ? ((int)blockIdx.x + 1) : 16;
    for (int jt = 0; jt < ntiles; jt++) {
        const int t0 = jt << 6;
        __syncthreads();
#pragma unroll
        for (int c = 0; c < 16; c += 4) {
            float4 kv = *(const float4*)(KT + base + ((size_t)(t0 + lr) << 6) + ld4 + c);
            KP[(ld4 + c + 0) * 68 + lr] = kv.x;
            KP[(ld4 + c + 1) * 68 + lr] = kv.y;
            KP[(ld4 + c + 2) * 68 + lr] = kv.z;
            KP[(ld4 + c + 3) * 68 + lr] = kv.w;
            float4 vv = *(const float4*)(V + base + ((size_t)(t0 + lr) << 6) + ld4 + c);
            *(float4*)&Vs[lr * 68 + ld4 + c] = vv;
        }
        __syncthreads();

        float sc[4][4];
#pragma unroll
        for (int i = 0; i < 4; i++)
#pragma unroll
            for (int j = 0; j < 4; j++) sc[i][j] = 0.f;
#pragma unroll 16
        for (int d = 0; d < 64; d++) {
            float4 qv = *(const float4*)&Qd[d * 68 + (ty << 2)];
            float4 kv = *(const float4*)&KP[d * 68 + (tx << 2)];
            const float qa[4] = {qv.x, qv.y, qv.z, qv.w};
            const float ka[4] = {kv.x, kv.y, kv.z, kv.w};
#pragma unroll
            for (int i = 0; i < 4; i++)
#pragma unroll
                for (int j = 0; j < 4; j++)
                    sc[i][j] = fmaf(qa[i], ka[j], sc[i][j]);
        }
        __syncthreads();

        float p[4][4];
#pragma unroll
        for (int i = 0; i < 4; i++) {
            const int srow = s0 + (ty << 2) + i;
            float mx = -INFINITY;
#pragma unroll
            for (int j = 0; j < 4; j++) {
                float v = sc[i][j] * 0.125f;
                if (causal && (t0 + (tx << 2) + j > srow)) v = -INFINITY;
                sc[i][j] = v;
                mx = fmaxf(mx, v);
            }
            mx = fmaxf(mx, __shfl_xor_sync(0xffffffffu, mx, 1));
            mx = fmaxf(mx, __shfl_xor_sync(0xffffffffu, mx, 2));
            mx = fmaxf(mx, __shfl_xor_sync(0xffffffffu, mx, 4));
            mx = fmaxf(mx, __shfl_xor_sync(0xffffffffu, mx, 8));
            const float mnew = fmaxf(m[i], mx);
            const float corr = __expf(m[i] - mnew);
            m[i] = mnew;
            float rs = 0.f;
#pragma unroll
            for (int j = 0; j < 4; j++) {
                const float pe = __expf(sc[i][j] - mnew);
                p[i][j] = pe;
                rs += pe;
            }
            rs += __shfl_xor_sync(0xffffffffu, rs, 1);
            rs += __shfl_xor_sync(0xffffffffu, rs, 2);
            rs += __shfl_xor_sync(0xffffffffu, rs, 4);
            rs += __shfl_xor_sync(0xffffffffu, rs, 8);
            l[i] = l[i] * corr + rs;
#pragma unroll
            for (int j = 0; j < 4; j++) o[i][j] *= corr;
        }

#pragma unroll
        for (int j = 0; j < 4; j++) {
            float4 pv = make_float4(p[0][j], p[1][j], p[2][j], p[3][j]);
            *(float4*)&KP[((tx << 2) + j) * 68 + (ty << 2)] = pv;
        }
        __syncthreads();

#pragma unroll 16
        for (int t = 0; t < 64; t++) {
            float4 pf = *(const float4*)&KP[t * 68 + (ty << 2)];
            float4 vf = *(const float4*)&Vs[t * 68 + (tx << 2)];
            const float pa[4] = {pf.x, pf.y, pf.z, pf.w};
            const float va[4] = {vf.x, vf.y, vf.z, vf.w};
#pragma unroll
            for (int i = 0; i < 4; i++)
#pragma unroll
                for (int j = 0; j < 4; j++)
                    o[i][j] = fmaf(pa[i], va[j], o[i][j]);
        }
    }

    const int h = hb >> 2, b = hb & 3;
#pragma unroll
    for (int i = 0; i < 4; i++) {
        const int s = s0 + (ty << 2) + i;
        const float invl = 1.f / l[i];
        const size_t row = ((size_t)((h >> 2) * 1024 + (h & 3) * 256 + b * 64 + (s >> 4)) << 10)
                         + ((s & 15) << 6);
        float4 ov = make_float4(o[i][0] * invl, o[i][1] * invl, o[i][2] * invl, o[i][3] * invl);
        *(float4*)(O2 + row + (tx << 2)) = ov;
    }
}

// ---------------- LayerNorm over (S,E) slab per batch ------------------------
__global__ void ln_part_kernel(const float* __restrict__ X)
{
    __shared__ double sd[256];
    __shared__ double sq[256];
    const int tid = threadIdx.x;
    const float4* p = (const float4*)(X + ((size_t)blockIdx.x << 14));
    float s = 0.f, q = 0.f;
#pragma unroll
    for (int it = 0; it < 16; it++) {
        float4 v = p[it * 256 + tid];
        s += v.x + v.y + v.z + v.w;
        q += v.x * v.x + v.y * v.y + v.z * v.z + v.w * v.w;
    }
    sd[tid] = (double)s; sq[tid] = (double)q;
    __syncthreads();
    for (int off = 128; off > 0; off >>= 1) {
        if (tid < off) { sd[tid] += sd[tid + off]; sq[tid] += sq[tid + off]; }
        __syncthreads();
    }
    if (tid == 0) { g_part[blockIdx.x][0] = sd[0]; g_part[blockIdx.x][1] = sq[0]; }
}

__global__ void ln_final_kernel()
{
    const int b = threadIdx.x;
    if (b < 4) {
        double s = 0.0, q = 0.0;
        for (int i = 0; i < 64; i++) { s += g_part[b * 64 + i][0]; q += g_part[b * 64 + i][1]; }
        const double inv_n = 1.0 / 1048576.0;
        const double mean = s * inv_n;
        const double var = q * inv_n - mean * mean;
        g_stats[b][0] = (float)mean;
        g_stats[b][1] = (float)(1.0 / sqrt(var + 1e-5));
    }
}

__global__ void ln_apply_kernel(const float* __restrict__ X, const float* __restrict__ w,
                                const float* __restrict__ bb, float* __restrict__ Y)
{
    const size_t i = ((size_t)blockIdx.x * 256 + threadIdx.x) << 2;
    const int b = (int)(i >> 20);
    const float mean = g_stats[b][0], inv = g_stats[b][1];
    const size_t wi = i & 1048575;
    float4 x = *(const float4*)(X + i);
    float4 wv = *(const float4*)(w + wi);
    float4 bv = *(const float4*)(bb + wi);
    float4 y;
    y.x = (x.x - mean) * inv * wv.x + bv.x;
    y.y = (x.y - mean) * inv * wv.y + bv.y;
    y.z = (x.z - mean) * inv * wv.z + bv.z;
    y.w = (x.w - mean) * inv * wv.w + bv.w;
    *(float4*)(Y + i) = y;
}

// ---------------- driver -----------------------------------------------------
extern "C" void kernel_launch(void* const* d_in, const int* in_sizes, int n_in,
                              void* d_out, int out_size)
{
    const float* inputRes = (const float*)d_in[0];
    const float* outEnc   = (const float*)d_in[1];
    const float* Wq1 = (const float*)d_in[2];
    const float* Wk1 = (const float*)d_in[3];
    const float* Wv1 = (const float*)d_in[4];
    const float* Wo1 = (const float*)d_in[5];
    const float* Wq2 = (const float*)d_in[6];
    const float* Wk2 = (const float*)d_in[7];
    const float* Wv2 = (const float*)d_in[8];
    const float* Wo2 = (const float*)d_in[9];
    const float* ln1w = (const float*)d_in[10];
    const float* ln1b = (const float*)d_in[11];
    const float* ln2w = (const float*)d_in[12];
    const float* ln2b = (const float*)d_in[13];
    const float* ln3w = (const float*)d_in[14];
    const float* ln3b = (const float*)d_in[15];
    const float* W1 = (const float*)d_in[16];
    const float* b1 = (const float*)d_in[17];
    const float* W2 = (const float*)d_in[18];
    const float* b2 = (const float*)d_in[19];
    float* out = (float*)d_out;

    float *q, *kT, *v, *o2, *t1, *n1, *n2, *fc1;
    __half* ws;
    cudaGetSymbolAddress((void**)&q,   g_q);
    cudaGetSymbolAddress((void**)&kT,  g_kT);
    cudaGetSymbolAddress((void**)&v,   g_v);
    cudaGetSymbolAddress((void**)&o2,  g_o2);
    cudaGetSymbolAddress((void**)&t1,  g_t1);
    cudaGetSymbolAddress((void**)&n1,  g_n1);
    cudaGetSymbolAddress((void**)&n2,  g_n2);
    cudaGetSymbolAddress((void**)&fc1, g_fc1);
    cudaGetSymbolAddress((void**)&ws,  g_ws);

    const int FLASH_SMEM = 3 * 64 * 68 * 4;
    cudaFuncSetAttribute(flash_kernel, cudaFuncAttributeMaxDynamicSharedMemorySize, FLASH_SMEM);

    const int SMH = 4 * 5120 * 2;  // 40960 B
    cudaFuncSetAttribute(hf_gemm<0, false, false, false>, cudaFuncAttributeMaxDynamicSharedMemorySize, SMH);
    cudaFuncSetAttribute(hf_gemm<1, false, false, false>, cudaFuncAttributeMaxDynamicSharedMemorySize, SMH);
    cudaFuncSetAttribute(hf_gemm<-1, false, true, false>, cudaFuncAttributeMaxDynamicSharedMemorySize, SMH);
    cudaFuncSetAttribute(hf_gemm<-1, true, false, true >, cudaFuncAttributeMaxDynamicSharedMemorySize, SMH);
    cudaFuncSetAttribute(hf_gemm<-1, true, true,  false>, cudaFuncAttributeMaxDynamicSharedMemorySize, SMH);

    dim3 blk(256);

    // ---- pre-split weights into transposed fp16 planes ----
    wsplit_kernel<1><<<dim3(16, 16), blk>>>(Wq1, ws + OFF_WQ1, 1024, 1024);
    wsplit_kernel<1><<<dim3(16, 16), blk>>>(Wk1, ws + OFF_WK1, 1024, 1024);
    wsplit_kernel<1><<<dim3(16, 16), blk>>>(Wv1, ws + OFF_WV1, 1024, 1024);
    wsplit_kernel<0><<<dim3(16, 16), blk>>>(Wo1, ws + OFF_WO1, 1024, 1024);
    wsplit_kernel<1><<<dim3(16, 16), blk>>>(Wq2, ws + OFF_WQ2, 1024, 1024);
    wsplit_kernel<1><<<dim3(16, 16), blk>>>(Wk2, ws + OFF_WK2, 1024, 1024);
    wsplit_kernel<1><<<dim3(16, 16), blk>>>(Wv2, ws + OFF_WV2, 1024, 1024);
    wsplit_kernel<0><<<dim3(16, 16), blk>>>(Wo2, ws + OFF_WO2, 1024, 1024);
    wsplit_kernel<0><<<dim3(32, 16), blk>>>(W1,  ws + OFF_W1,  2048, 1024);
    wsplit_kernel<0><<<dim3(16, 32), blk>>>(W2,  ws + OFF_W2,  1024, 2048);

    dim3 g1024(8, 32), g2048(16, 32);

    // ---- MHA1 (self, causal) ----
    hf_gemm<0, false, false, false><<<g1024, blk, SMH>>>(outEnc, ws + OFF_WQ1, nullptr, nullptr, q,  1024, 1024);
    hf_gemm<1, false, false, false><<<g1024, blk, SMH>>>(outEnc, ws + OFF_WK1, nullptr, nullptr, kT, 1024, 1024);
    hf_gemm<0, false, false, false><<<g1024, blk, SMH>>>(outEnc, ws + OFF_WV1, nullptr, nullptr, v,  1024, 1024);
    flash_kernel<<<dim3(16, 64), blk, FLASH_SMEM>>>(q, kT, v, o2, 1);
    hf_gemm<-1, false, true, false><<<g1024, blk, SMH>>>(o2, ws + OFF_WO1, nullptr, outEnc, t1, 1024, 1024);
    ln_part_kernel<<<256, blk>>>(t1);
    ln_final_kernel<<<1, 32>>>();
    ln_apply_kernel<<<4096, blk>>>(t1, ln1w, ln1b, n1);

    // ---- MHA2 (cross) ----
    hf_gemm<0, false, false, false><<<g1024, blk, SMH>>>(n1,       ws + OFF_WQ2, nullptr, nullptr, q,  1024, 1024);
    hf_gemm<1, false, false, false><<<g1024, blk, SMH>>>(inputRes, ws + OFF_WK2, nullptr, nullptr, kT, 1024, 1024);
    hf_gemm<0, false, false, false><<<g1024, blk, SMH>>>(inputRes, ws + OFF_WV2, nullptr, nullptr, v,  1024, 1024);
    flash_kernel<<<dim3(16, 64), blk, FLASH_SMEM>>>(q, kT, v, o2, 0);
    hf_gemm<-1, false, true, false><<<g1024, blk, SMH>>>(o2, ws + OFF_WO2, nullptr, outEnc, t1, 1024, 1024);
    ln_part_kernel<<<256, blk>>>(t1);
    ln_final_kernel<<<1, 32>>>();
    ln_apply_kernel<<<4096, blk>>>(t1, ln2w, ln2b, n2);

    // ---- FFN ----
    hf_gemm<-1, true, false, true ><<<g2048, blk, SMH>>>(n2,  ws + OFF_W1, b1, nullptr, fc1, 2048, 1024);
    hf_gemm<-1, true, true,  false><<<g1024, blk, SMH>>>(fc1, ws + OFF_W2, b2, n2,      t1,  1024, 2048);
    ln_part_kernel<<<256, blk>>>(t1);
    ln_final_kernel<<<1, 32>>>();
    ln_apply_kernel<<<4096, blk>>>(t1, ln3w, ln3b, out);
}

// round 8
// speedup vs baseline: 1.8468x; 1.2658x over previous
#include <cuda_runtime.h>
#include <cuda_fp16.h>
#include <math.h>
#include <stdint.h>

#define N_ELEM 4194304  // 4*1024*1024

// ---------------- scratch (device globals) ----------------------------------
__device__ float  g_q [N_ELEM];
__device__ float  g_kT[N_ELEM];
__device__ float  g_v [N_ELEM];
__device__ float  g_o2[N_ELEM];
__device__ float  g_t1[N_ELEM];
__device__ float  g_n1[N_ELEM];
__device__ float  g_n2[N_ELEM];
__device__ float  g_fc1[4096 * 2048];
__device__ double g_part[256][2];
__device__ float  g_stats[4][2];
// split fp16 weight planes: per weight [2][N][K]
__device__ __half g_ws[25165824];  // 48 MB

#define OFF_WQ1 0
#define OFF_WK1 2097152
#define OFF_WV1 4194304
#define OFF_WO1 6291456
#define OFF_WQ2 8388608
#define OFF_WK2 10485760
#define OFF_WV2 12582912
#define OFF_WO2 14680064
#define OFF_W1  16777216
#define OFF_W2  20971520

// ---------------- mma.sync fp16 helper ---------------------------------------
__device__ __forceinline__ void mma_f16(float* c, const unsigned* a, const unsigned* b) {
    asm volatile(
        "mma.sync.aligned.m16n8k16.row.col.f32.f16.f16.f32 "
        "{%0,%1,%2,%3}, {%4,%5,%6,%7}, {%8,%9}, {%0,%1,%2,%3};\n"
        : "+f"(c[0]), "+f"(c[1]), "+f"(c[2]), "+f"(c[3])
        : "r"(a[0]), "r"(a[1]), "r"(a[2]), "r"(a[3]), "r"(b[0]), "r"(b[1]));
}

__device__ __forceinline__ unsigned pack_h2(float a, float b) {
    __half2 h = __floats2half2_rn(a, b);
    return *(unsigned*)&h;
}

// ---------------- weight transpose + 2-way fp16 split ------------------------
template<int PROJ>
__global__ __launch_bounds__(256)
void wsplit_kernel(const float* __restrict__ W, __half* __restrict__ out,
                   int N, int K)
{
    __shared__ float t[64][65];
    const int tid = threadIdx.x;
    const int n0 = blockIdx.x << 6, k0 = blockIdx.y << 6;
#pragma unroll
    for (int r = 0; r < 4; r++) {
        const int flat = tid + (r << 8);
        const int kr = flat >> 4, nc = (flat & 15) << 2;
        const float* src;
        if (PROJ) src = W + ((size_t)((n0 + nc) >> 6) << 16) + ((size_t)(k0 + kr) << 6) + ((n0 + nc) & 63);
        else      src = W + (size_t)(k0 + kr) * N + n0 + nc;
        float4 v = *(const float4*)src;
        t[kr][nc] = v.x; t[kr][nc + 1] = v.y; t[kr][nc + 2] = v.z; t[kr][nc + 3] = v.w;
    }
    __syncthreads();
    const size_t ps = (size_t)N * K;
#pragma unroll
    for (int r = 0; r < 4; r++) {
        const int flat = tid + (r << 8);
        const int nr = flat >> 4, kc = (flat & 15) << 2;
        unsigned short u0[4], u1[4];
#pragma unroll
        for (int j = 0; j < 4; j++) {
            float x = t[kc + j][nr];
            __half h0 = __float2half_rn(x);
            float r1 = x - __half2float(h0);
            __half h1 = __float2half_rn(r1);
            u0[j] = __half_as_ushort(h0);
            u1[j] = __half_as_ushort(h1);
        }
        const size_t dst = (size_t)(n0 + nr) * K + k0 + kc;
        *(uint2*)(out + dst)      = make_uint2(u0[0] | (u0[1] << 16), u0[2] | (u0[3] << 16));
        *(uint2*)(out + ps + dst) = make_uint2(u1[0] | (u1[1] << 16), u1[2] | (u1[3] << 16));
    }
}

// ---------------- fp16 2-plane tensor-core GEMM (unchanged from R7) ----------
template<int MODE, bool BIAS, bool RES, bool RELU>
__global__ __launch_bounds__(256)
void hf_gemm(const float* __restrict__ A, const __half* __restrict__ Bp,
             const float* __restrict__ bias, const float* __restrict__ res,
             float* __restrict__ C, int N, int K)
{
    extern __shared__ __half smp[];
    __half* Asm = smp;
    __half* Bsm = smp + 2 * 5120;

    const int tid  = threadIdx.x;
    const int lane = tid & 31, wid = tid >> 5;
    const int g = lane >> 2, tig = lane & 3;
    const int wm = wid >> 2, wn = wid & 3;
    const int m0 = blockIdx.y << 7, n0 = blockIdx.x << 7;
    const size_t bstride = (size_t)N * K;

    float acc[4][4][4];
#pragma unroll
    for (int mt = 0; mt < 4; mt++)
#pragma unroll
        for (int nt = 0; nt < 4; nt++)
#pragma unroll
            for (int c = 0; c < 4; c++) acc[mt][nt][c] = 0.f;

    constexpr int PI[3] = {0, 1, 0};
    constexpr int PJ[3] = {0, 0, 1};

    float4 pa[4];
    uint4  pb[2][2];

#pragma unroll
    for (int r = 0; r < 4; r++) {
        const int flat = tid + (r << 8);
        const int row = flat >> 3, c4 = (flat & 7) << 2;
        pa[r] = *(const float4*)(A + (size_t)(m0 + row) * K + c4);
    }
#pragma unroll
    for (int p = 0; p < 2; p++)
#pragma unroll
        for (int r = 0; r < 2; r++) {
            const int flat = tid + (r << 8);
            const int row = flat >> 2, cs = (flat & 3) << 3;
            pb[p][r] = *(const uint4*)(Bp + (size_t)p * bstride + (size_t)(n0 + row) * K + cs);
        }

    for (int k0 = 0;;) {
#pragma unroll
        for (int r = 0; r < 4; r++) {
            const int flat = tid + (r << 8);
            const int row = flat >> 3, c4 = (flat & 7) << 2;
            float x[4] = {pa[r].x, pa[r].y, pa[r].z, pa[r].w};
            unsigned short u0[4], u1[4];
#pragma unroll
            for (int j = 0; j < 4; j++) {
                __half h0 = __float2half_rn(x[j]);
                float r1 = x[j] - __half2float(h0);
                __half h1 = __float2half_rn(r1);
                u0[j] = __half_as_ushort(h0);
                u1[j] = __half_as_ushort(h1);
            }
            const int off = row * 40 + c4;
            *(uint2*)(Asm + off)        = make_uint2(u0[0] | (u0[1] << 16), u0[2] | (u0[3] << 16));
            *(uint2*)(Asm + 5120 + off) = make_uint2(u1[0] | (u1[1] << 16), u1[2] | (u1[3] << 16));
        }
#pragma unroll
        for (int p = 0; p < 2; p++)
#pragma unroll
            for (int r = 0; r < 2; r++) {
                const int flat = tid + (r << 8);
                const int row = flat >> 2, cs = (flat & 3) << 3;
                *(uint4*)(Bsm + p * 5120 + row * 40 + cs) = pb[p][r];
            }
        __syncthreads();

        const int kn = k0 + 32;
        if (kn < K) {
#pragma unroll
            for (int r = 0; r < 4; r++) {
                const int flat = tid + (r << 8);
                const int row = flat >> 3, c4 = (flat & 7) << 2;
                pa[r] = *(const float4*)(A + (size_t)(m0 + row) * K + kn + c4);
            }
#pragma unroll
            for (int p = 0; p < 2; p++)
#pragma unroll
                for (int r = 0; r < 2; r++) {
                    const int flat = tid + (r << 8);
                    const int row = flat >> 2, cs = (flat & 3) << 3;
                    pb[p][r] = *(const uint4*)(Bp + (size_t)p * bstride
                                               + (size_t)(n0 + row) * K + kn + cs);
                }
        }

#pragma unroll
        for (int pp = 0; pp < 3; pp++) {
            const __half* Ap = Asm + PI[pp] * 5120;
            const __half* Bq = Bsm + PJ[pp] * 5120;
#pragma unroll
            for (int kt = 0; kt < 2; kt++) {
                const int kb = kt << 4;
                unsigned af[4][4], bf_[4][2];
#pragma unroll
                for (int mt = 0; mt < 4; mt++) {
                    const int rb = (wm << 6) + (mt << 4);
                    af[mt][0] = *(const unsigned*)(Ap + (rb + g) * 40 + kb + (tig << 1));
                    af[mt][1] = *(const unsigned*)(Ap + (rb + g + 8) * 40 + kb + (tig << 1));
                    af[mt][2] = *(const unsigned*)(Ap + (rb + g) * 40 + kb + 8 + (tig << 1));
                    af[mt][3] = *(const unsigned*)(Ap + (rb + g + 8) * 40 + kb + 8 + (tig << 1));
                }
#pragma unroll
                for (int nt = 0; nt < 4; nt++) {
                    const int nb = (wn << 5) + (nt << 3);
                    bf_[nt][0] = *(const unsigned*)(Bq + (nb + g) * 40 + kb + (tig << 1));
                    bf_[nt][1] = *(const unsigned*)(Bq + (nb + g) * 40 + kb + 8 + (tig << 1));
                }
#pragma unroll
                for (int mt = 0; mt < 4; mt++)
#pragma unroll
                    for (int nt = 0; nt < 4; nt++)
                        mma_f16(acc[mt][nt], af[mt], bf_[nt]);
            }
        }

        k0 = kn;
        if (k0 >= K) break;
        __syncthreads();
    }

#pragma unroll
    for (int mt = 0; mt < 4; mt++) {
#pragma unroll
        for (int nt = 0; nt < 4; nt++) {
            const int m = m0 + (wm << 6) + (mt << 4) + g;
            const int n = n0 + (wn << 5) + (nt << 3) + (tig << 1);
            const float* c = acc[mt][nt];
            float2 v0 = make_float2(c[0], c[1]);
            float2 v1 = make_float2(c[2], c[3]);

            if constexpr (MODE < 0) {
                if (BIAS) {
                    float2 bv = *(const float2*)(bias + n);
                    v0.x += bv.x; v0.y += bv.y; v1.x += bv.x; v1.y += bv.y;
                }
                if (RES) {
                    float2 r0 = *(const float2*)(res + (size_t)m * N + n);
                    float2 r1 = *(const float2*)(res + (size_t)(m + 8) * N + n);
                    v0.x += r0.x; v0.y += r0.y; v1.x += r1.x; v1.y += r1.y;
                }
                if (RELU) {
                    v0.x = fmaxf(v0.x, 0.f); v0.y = fmaxf(v0.y, 0.f);
                    v1.x = fmaxf(v1.x, 0.f); v1.y = fmaxf(v1.y, 0.f);
                }
                *(float2*)(C + (size_t)m * N + n) = v0;
                *(float2*)(C + (size_t)(m + 8) * N + n) = v1;
            } else if constexpr (MODE == 0) {
                const int b = m >> 10, s = m & 1023;
                const int h = n >> 6, d = n & 63;
                const size_t hb = (size_t)(h * 4 + b);
                *(float2*)(C + (((hb << 10) + s) << 6) + d) = v0;
                *(float2*)(C + (((hb << 10) + s + 8) << 6) + d) = v1;
            } else {
                const int b = m >> 10, s = m & 1023;
                const int h = n >> 6, d = n & 63;
                const size_t hb = (size_t)(h * 4 + b);
                const int t0a = ((s & 15) << 6) | d;
                const int t0b = (((s + 8) & 15) << 6) | d;
                C[((hb << 10) + t0a)     * 64 + (s >> 4)]       = c[0];
                C[((hb << 10) + t0a + 1) * 64 + (s >> 4)]       = c[1];
                C[((hb << 10) + t0b)     * 64 + ((s + 8) >> 4)] = c[2];
                C[((hb << 10) + t0b + 1) * 64 + ((s + 8) >> 4)] = c[3];
            }
        }
    }
}

// ---------------- tensor-core flash attention --------------------------------
// 64(s)x64(t) tiles, 8 warps = 4 m-strips x 2 t-halves. fp16 2-plane splits
// for Q/K (3-pass QK) and P/V (3-pass PV).  score(s,t)=dot64(Q[s],KT[t])/8.
__global__ __launch_bounds__(256)
void flash_mma_kernel(const float* __restrict__ Q, const float* __restrict__ KT,
                      const float* __restrict__ V, float* __restrict__ O2, int causal)
{
    extern __shared__ char fsm[];
    __half* Kh = (__half*)fsm;           // [64][72]
    __half* Kl = Kh + 4608;
    __half* Vh = Kh + 9216;              // transposed [dv][72] with XOR swizzle
    __half* Vl = Kh + 13824;
    float* smax = (float*)(fsm + 36864); // [2][64]
    float* ssum = smax + 128;            // [2][64]
    float* sm_o = (float*)fsm;           // epilogue overlay [2][64][72]

    const int tid = threadIdx.x;
    const int lane = tid & 31, wid = tid >> 5;
    const int g = lane >> 2, tig = lane & 3;
    const int wm = wid >> 1, wn = wid & 1;
    const int s0 = blockIdx.x << 6;
    const int hb = blockIdx.y;
    const size_t base = (size_t)hb << 16;
    const int mrow = (wm << 4) + g;      // local m row (0..63)

    // ---- stage Q (x0.125), split into Kh/Kl area ----
#pragma unroll
    for (int it = 0; it < 4; it++) {
        const int flat = tid + (it << 8);
        const int r = flat >> 4, c4 = (flat & 15) << 2;
        float4 qv = *(const float4*)(Q + base + ((size_t)(s0 + r) << 6) + c4);
        float x[4] = {qv.x * 0.125f, qv.y * 0.125f, qv.z * 0.125f, qv.w * 0.125f};
        unsigned short u0[4], u1[4];
#pragma unroll
        for (int j = 0; j < 4; j++) {
            __half h0 = __float2half_rn(x[j]);
            float r1 = x[j] - __half2float(h0);
            u0[j] = __half_as_ushort(h0);
            u1[j] = __half_as_ushort(__float2half_rn(r1));
        }
        *(uint2*)&Kh[r * 72 + c4] = make_uint2(u0[0] | (u0[1] << 16), u0[2] | (u0[3] << 16));
        *(uint2*)&Kl[r * 72 + c4] = make_uint2(u1[0] | (u1[1] << 16), u1[2] | (u1[3] << 16));
    }
    __syncthreads();

    // ---- load persistent Q A-frags ----
    unsigned qh[4][4], ql[4][4];
#pragma unroll
    for (int kt = 0; kt < 4; kt++) {
        const int kb = kt << 4;
        qh[kt][0] = *(const unsigned*)&Kh[mrow * 72 + kb + (tig << 1)];
        qh[kt][1] = *(const unsigned*)&Kh[(mrow + 8) * 72 + kb + (tig << 1)];
        qh[kt][2] = *(const unsigned*)&Kh[mrow * 72 + kb + 8 + (tig << 1)];
        qh[kt][3] = *(const unsigned*)&Kh[(mrow + 8) * 72 + kb + 8 + (tig << 1)];
        ql[kt][0] = *(const unsigned*)&Kl[mrow * 72 + kb + (tig << 1)];
        ql[kt][1] = *(const unsigned*)&Kl[(mrow + 8) * 72 + kb + (tig << 1)];
        ql[kt][2] = *(const unsigned*)&Kl[mrow * 72 + kb + 8 + (tig << 1)];
        ql[kt][3] = *(const unsigned*)&Kl[(mrow + 8) * 72 + kb + 8 + (tig << 1)];
    }

    float o[8][4];
#pragma unroll
    for (int nt = 0; nt < 8; nt++)
#pragma unroll
        for (int c = 0; c < 4; c++) o[nt][c] = 0.f;
    float m0 = -INFINITY, m1 = -INFINITY, l0 = 0.f, l1 = 0.f;

    const int row0 = s0 + mrow, row1 = row0 + 8;
    const int ntiles = causal ? ((int)blockIdx.x + 1) : 16;

    for (int jt = 0; jt < ntiles; jt++) {
        const int t0 = jt << 6;
        __syncthreads();  // S1: prev PV/reduction reads complete

        // ---- stage K planes ----
#pragma unroll
        for (int it = 0; it < 4; it++) {
            const int flat = tid + (it << 8);
            const int r = flat >> 4, c4 = (flat & 15) << 2;
            float4 kv = *(const float4*)(KT + base + ((size_t)(t0 + r) << 6) + c4);
            float x[4] = {kv.x, kv.y, kv.z, kv.w};
            unsigned short u0[4], u1[4];
#pragma unroll
            for (int j = 0; j < 4; j++) {
                __half h0 = __float2half_rn(x[j]);
                float r1 = x[j] - __half2float(h0);
                u0[j] = __half_as_ushort(h0);
                u1[j] = __half_as_ushort(__float2half_rn(r1));
            }
            *(uint2*)&Kh[r * 72 + c4] = make_uint2(u0[0] | (u0[1] << 16), u0[2] | (u0[3] << 16));
            *(uint2*)&Kl[r * 72 + c4] = make_uint2(u1[0] | (u1[1] << 16), u1[2] | (u1[3] << 16));
        }
        // ---- stage V planes (transposed + XOR swizzle) ----
#pragma unroll
        for (int it = 0; it < 4; it++) {
            const int flat = tid + (it << 8);
            const int tr = flat >> 4, dv4 = (flat & 15) << 2;
            float4 vv = *(const float4*)(V + base + ((size_t)(t0 + tr) << 6) + dv4);
            float x[4] = {vv.x, vv.y, vv.z, vv.w};
#pragma unroll
            for (int j = 0; j < 4; j++) {
                const int dv = dv4 + j;
                const int sw = ((dv >> 2) & 7) << 3;
                const int idx = dv * 72 + (tr ^ sw);
                __half h0 = __float2half_rn(x[j]);
                float r1 = x[j] - __half2float(h0);
                Vh[idx] = h0;
                Vl[idx] = __float2half_rn(r1);
            }
        }
        __syncthreads();  // S2

        // ---- QK mma (3 passes: Qh*Kh, Ql*Kh, Qh*Kl) ----
        float sc[4][4];
#pragma unroll
        for (int nt = 0; nt < 4; nt++)
#pragma unroll
            for (int c = 0; c < 4; c++) sc[nt][c] = 0.f;
#pragma unroll
        for (int kt = 0; kt < 4; kt++) {
            const int kb = kt << 4;
#pragma unroll
            for (int nt = 0; nt < 4; nt++) {
                const int nr = (wn << 5) + (nt << 3) + g;
                unsigned b[2];
                b[0] = *(const unsigned*)&Kh[nr * 72 + kb + (tig << 1)];
                b[1] = *(const unsigned*)&Kh[nr * 72 + kb + 8 + (tig << 1)];
                mma_f16(sc[nt], qh[kt], b);
                mma_f16(sc[nt], ql[kt], b);
            }
        }
#pragma unroll
        for (int kt = 0; kt < 4; kt++) {
            const int kb = kt << 4;
#pragma unroll
            for (int nt = 0; nt < 4; nt++) {
                const int nr = (wn << 5) + (nt << 3) + g;
                unsigned b[2];
                b[0] = *(const unsigned*)&Kl[nr * 72 + kb + (tig << 1)];
                b[1] = *(const unsigned*)&Kl[nr * 72 + kb + 8 + (tig << 1)];
                mma_f16(sc[nt], qh[kt], b);
            }
        }

        // ---- mask + row max ----
        float mx0 = -INFINITY, mx1 = -INFINITY;
#pragma unroll
        for (int nt = 0; nt < 4; nt++) {
            const int col = t0 + (wn << 5) + (nt << 3) + (tig << 1);
            if (causal) {
                if (col > row0)     sc[nt][0] = -INFINITY;
                if (col + 1 > row0) sc[nt][1] = -INFINITY;
                if (col > row1)     sc[nt][2] = -INFINITY;
                if (col + 1 > row1) sc[nt][3] = -INFINITY;
            }
            mx0 = fmaxf(mx0, fmaxf(sc[nt][0], sc[nt][1]));
            mx1 = fmaxf(mx1, fmaxf(sc[nt][2], sc[nt][3]));
        }
        mx0 = fmaxf(mx0, __shfl_xor_sync(0xffffffffu, mx0, 1));
        mx0 = fmaxf(mx0, __shfl_xor_sync(0xffffffffu, mx0, 2));
        mx1 = fmaxf(mx1, __shfl_xor_sync(0xffffffffu, mx1, 1));
        mx1 = fmaxf(mx1, __shfl_xor_sync(0xffffffffu, mx1, 2));
        smax[(wn << 6) + mrow] = mx0;
        smax[(wn << 6) + mrow + 8] = mx1;
        __syncthreads();  // S3

        const float mn0 = fmaxf(m0, fmaxf(smax[mrow], smax[64 + mrow]));
        const float mn1 = fmaxf(m1, fmaxf(smax[mrow + 8], smax[64 + mrow + 8]));
        const float cr0 = __expf(m0 - mn0);
        const float cr1 = __expf(m1 - mn1);
        m0 = mn0; m1 = mn1;
#pragma unroll
        for (int nt = 0; nt < 8; nt++) {
            o[nt][0] *= cr0; o[nt][1] *= cr0;
            o[nt][2] *= cr1; o[nt][3] *= cr1;
        }
        float p[4][4];
        float rs0 = 0.f, rs1 = 0.f;
#pragma unroll
        for (int nt = 0; nt < 4; nt++) {
            p[nt][0] = __expf(sc[nt][0] - mn0);
            p[nt][1] = __expf(sc[nt][1] - mn0);
            p[nt][2] = __expf(sc[nt][2] - mn1);
            p[nt][3] = __expf(sc[nt][3] - mn1);
            rs0 += p[nt][0] + p[nt][1];
            rs1 += p[nt][2] + p[nt][3];
        }
        rs0 += __shfl_xor_sync(0xffffffffu, rs0, 1);
        rs0 += __shfl_xor_sync(0xffffffffu, rs0, 2);
        rs1 += __shfl_xor_sync(0xffffffffu, rs1, 1);
        rs1 += __shfl_xor_sync(0xffffffffu, rs1, 2);
        ssum[(wn << 6) + mrow] = rs0;
        ssum[(wn << 6) + mrow + 8] = rs1;
        __syncthreads();  // S4
        l0 = l0 * cr0 + ssum[mrow] + ssum[64 + mrow];
        l1 = l1 * cr1 + ssum[mrow + 8] + ssum[64 + mrow + 8];

        // ---- P -> A frags (hi + residual lo) ----
        unsigned ah[2][4], al[2][4];
#pragma unroll
        for (int kc = 0; kc < 2; kc++) {
            const int ta = kc << 1, tb = ta + 1;
            float h00 = __half2float(__float2half_rn(p[ta][0]));
            float h01 = __half2float(__float2half_rn(p[ta][1]));
            float h02 = __half2float(__float2half_rn(p[ta][2]));
            float h03 = __half2float(__float2half_rn(p[ta][3]));
            float h10 = __half2float(__float2half_rn(p[tb][0]));
            float h11 = __half2float(__float2half_rn(p[tb][1]));
            float h12 = __half2float(__float2half_rn(p[tb][2]));
            float h13 = __half2float(__float2half_rn(p[tb][3]));
            ah[kc][0] = pack_h2(h00, h01);
            ah[kc][1] = pack_h2(h02, h03);
            ah[kc][2] = pack_h2(h10, h11);
            ah[kc][3] = pack_h2(h12, h13);
            al[kc][0] = pack_h2(p[ta][0] - h00, p[ta][1] - h01);
            al[kc][1] = pack_h2(p[ta][2] - h02, p[ta][3] - h03);
            al[kc][2] = pack_h2(p[tb][0] - h10, p[tb][1] - h11);
            al[kc][3] = pack_h2(p[tb][2] - h12, p[tb][3] - h13);
        }

        // ---- PV mma (3 passes: Ph*Vh, Pl*Vh, Ph*Vl) over this warp's t-half ----
#pragma unroll
        for (int nt = 0; nt < 8; nt++) {
            const int dv = (nt << 3) + g;
            const int sw = ((dv >> 2) & 7) << 3;
            const int rb = dv * 72;
#pragma unroll
            for (int kc = 0; kc < 2; kc++) {
                const int kg = (wn << 5) + (kc << 4);
                unsigned vb[2], wb[2];
                vb[0] = *(const unsigned*)&Vh[rb + ((kg ^ sw) + (tig << 1))];
                vb[1] = *(const unsigned*)&Vh[rb + (((kg + 8) ^ sw) + (tig << 1))];
                mma_f16(o[nt], ah[kc], vb);
                mma_f16(o[nt], al[kc], vb);
                wb[0] = *(const unsigned*)&Vl[rb + ((kg ^ sw) + (tig << 1))];
                wb[1] = *(const unsigned*)&Vl[rb + (((kg + 8) ^ sw) + (tig << 1))];
                mma_f16(o[nt], ah[kc], wb);
            }
        }
    }

    // ---- epilogue: scale by 1/l, pair-sum over wn, write O2 concat layout ----
    const float il0 = 1.f / l0, il1 = 1.f / l1;
#pragma unroll
    for (int nt = 0; nt < 8; nt++) {
        o[nt][0] *= il0; o[nt][1] *= il0;
        o[nt][2] *= il1; o[nt][3] *= il1;
    }
    __syncthreads();  // loop smem reads done before overlay writes
    float* po = sm_o + wn * 4608;
#pragma unroll
    for (int nt = 0; nt < 8; nt++) {
        const int dv = (nt << 3) + (tig << 1);
        *(float2*)&po[mrow * 72 + dv]       = make_float2(o[nt][0], o[nt][1]);
        *(float2*)&po[(mrow + 8) * 72 + dv] = make_float2(o[nt][2], o[nt][3]);
    }
    __syncthreads();
    if (wn == 0) {
        const int h = hb >> 2, b = hb & 3;
        const int r = lane >> 1;
        const int dvh = (lane & 1) << 5;
        const int row = (wm << 4) + r;
        const int s = s0 + row;
        const size_t orow = ((size_t)((h >> 2) * 1024 + (h & 3) * 256 + b * 64 + (s >> 4)) << 10)
                          + ((s & 15) << 6);
#pragma unroll
        for (int i = 0; i < 8; i++) {
            const int dv = dvh + (i << 2);
            float4 a = *(const float4*)&sm_o[row * 72 + dv];
            float4 bb = *(const float4*)&sm_o[4608 + row * 72 + dv];
            float4 vv = make_float4(a.x + bb.x, a.y + bb.y, a.z + bb.z, a.w + bb.w);
            *(float4*)(O2 + orow + dv) = vv;
        }
    }
}

// ---------------- LayerNorm over (S,E) slab per batch ------------------------
__global__ void ln_part_kernel(const float* __restrict__ X)
{
    __shared__ double sd[256];
    __shared__ double sq[256];
    const int tid = threadIdx.x;
    const float4* p = (const float4*)(X + ((size_t)blockIdx.x << 14));
    float s = 0.f, q = 0.f;
#pragma unroll
    for (int it = 0; it < 16; it++) {
        float4 v = p[it * 256 + tid];
        s += v.x + v.y + v.z + v.w;
        q += v.x * v.x + v.y * v.y + v.z * v.z + v.w * v.w;
    }
    sd[tid] = (double)s; sq[tid] = (double)q;
    __syncthreads();
    for (int off = 128; off > 0; off >>= 1) {
        if (tid < off) { sd[tid] += sd[tid + off]; sq[tid] += sq[tid + off]; }
        __syncthreads();
    }
    if (tid == 0) { g_part[blockIdx.x][0] = sd[0]; g_part[blockIdx.x][1] = sq[0]; }
}

__global__ void ln_final_kernel()
{
    const int b = threadIdx.x;
    if (b < 4) {
        double s = 0.0, q = 0.0;
        for (int i = 0; i < 64; i++) { s += g_part[b * 64 + i][0]; q += g_part[b * 64 + i][1]; }
        const double inv_n = 1.0 / 1048576.0;
        const double mean = s * inv_n;
        const double var = q * inv_n - mean * mean;
        g_stats[b][0] = (float)mean;
        g_stats[b][1] = (float)(1.0 / sqrt(var + 1e-5));
    }
}

__global__ void ln_apply_kernel(const float* __restrict__ X, const float* __restrict__ w,
                                const float* __restrict__ bb, float* __restrict__ Y)
{
    const size_t i = ((size_t)blockIdx.x * 256 + threadIdx.x) << 2;
    const int b = (int)(i >> 20);
    const float mean = g_stats[b][0], inv = g_stats[b][1];
    const size_t wi = i & 1048575;
    float4 x = *(const float4*)(X + i);
    float4 wv = *(const float4*)(w + wi);
    float4 bv = *(const float4*)(bb + wi);
    float4 y;
    y.x = (x.x - mean) * inv * wv.x + bv.x;
    y.y = (x.y - mean) * inv * wv.y + bv.y;
    y.z = (x.z - mean) * inv * wv.z + bv.z;
    y.w = (x.w - mean) * inv * wv.w + bv.w;
    *(float4*)(Y + i) = y;
}

// ---------------- driver -----------------------------------------------------
extern "C" void kernel_launch(void* const* d_in, const int* in_sizes, int n_in,
                              void* d_out, int out_size)
{
    const float* inputRes = (const float*)d_in[0];
    const float* outEnc   = (const float*)d_in[1];
    const float* Wq1 = (const float*)d_in[2];
    const float* Wk1 = (const float*)d_in[3];
    const float* Wv1 = (const float*)d_in[4];
    const float* Wo1 = (const float*)d_in[5];
    const float* Wq2 = (const float*)d_in[6];
    const float* Wk2 = (const float*)d_in[7];
    const float* Wv2 = (const float*)d_in[8];
    const float* Wo2 = (const float*)d_in[9];
    const float* ln1w = (const float*)d_in[10];
    const float* ln1b = (const float*)d_in[11];
    const float* ln2w = (const float*)d_in[12];
    const float* ln2b = (const float*)d_in[13];
    const float* ln3w = (const float*)d_in[14];
    const float* ln3b = (const float*)d_in[15];
    const float* W1 = (const float*)d_in[16];
    const float* b1 = (const float*)d_in[17];
    const float* W2 = (const float*)d_in[18];
    const float* b2 = (const float*)d_in[19];
    float* out = (float*)d_out;

    float *q, *kT, *v, *o2, *t1, *n1, *n2, *fc1;
    __half* ws;
    cudaGetSymbolAddress((void**)&q,   g_q);
    cudaGetSymbolAddress((void**)&kT,  g_kT);
    cudaGetSymbolAddress((void**)&v,   g_v);
    cudaGetSymbolAddress((void**)&o2,  g_o2);
    cudaGetSymbolAddress((void**)&t1,  g_t1);
    cudaGetSymbolAddress((void**)&n1,  g_n1);
    cudaGetSymbolAddress((void**)&n2,  g_n2);
    cudaGetSymbolAddress((void**)&fc1, g_fc1);
    cudaGetSymbolAddress((void**)&ws,  g_ws);

    const int FSM = 37888;
    cudaFuncSetAttribute(flash_mma_kernel, cudaFuncAttributeMaxDynamicSharedMemorySize, FSM);

    const int SMH = 4 * 5120 * 2;  // 40960 B
    cudaFuncSetAttribute(hf_gemm<0, false, false, false>, cudaFuncAttributeMaxDynamicSharedMemorySize, SMH);
    cudaFuncSetAttribute(hf_gemm<1, false, false, false>, cudaFuncAttributeMaxDynamicSharedMemorySize, SMH);
    cudaFuncSetAttribute(hf_gemm<-1, false, true, false>, cudaFuncAttributeMaxDynamicSharedMemorySize, SMH);
    cudaFuncSetAttribute(hf_gemm<-1, true, false, true >, cudaFuncAttributeMaxDynamicSharedMemorySize, SMH);
    cudaFuncSetAttribute(hf_gemm<-1, true, true,  false>, cudaFuncAttributeMaxDynamicSharedMemorySize, SMH);

    dim3 blk(256);

    // ---- pre-split weights into transposed fp16 planes ----
    wsplit_kernel<1><<<dim3(16, 16), blk>>>(Wq1, ws + OFF_WQ1, 1024, 1024);
    wsplit_kernel<1><<<dim3(16, 16), blk>>>(Wk1, ws + OFF_WK1, 1024, 1024);
    wsplit_kernel<1><<<dim3(16, 16), blk>>>(Wv1, ws + OFF_WV1, 1024, 1024);
    wsplit_kernel<0><<<dim3(16, 16), blk>>>(Wo1, ws + OFF_WO1, 1024, 1024);
    wsplit_kernel<1><<<dim3(16, 16), blk>>>(Wq2, ws + OFF_WQ2, 1024, 1024);
    wsplit_kernel<1><<<dim3(16, 16), blk>>>(Wk2, ws + OFF_WK2, 1024, 1024);
    wsplit_kernel<1><<<dim3(16, 16), blk>>>(Wv2, ws + OFF_WV2, 1024, 1024);
    wsplit_kernel<0><<<dim3(16, 16), blk>>>(Wo2, ws + OFF_WO2, 1024, 1024);
    wsplit_kernel<0><<<dim3(32, 16), blk>>>(W1,  ws + OFF_W1,  2048, 1024);
    wsplit_kernel<0><<<dim3(16, 32), blk>>>(W2,  ws + OFF_W2,  1024, 2048);

    dim3 g1024(8, 32), g2048(16, 32);

    // ---- MHA1 (self, causal) ----
    hf_gemm<0, false, false, false><<<g1024, blk, SMH>>>(outEnc, ws + OFF_WQ1, nullptr, nullptr, q,  1024, 1024);
    hf_gemm<1, false, false, false><<<g1024, blk, SMH>>>(outEnc, ws + OFF_WK1, nullptr, nullptr, kT, 1024, 1024);
    hf_gemm<0, false, false, false><<<g1024, blk, SMH>>>(outEnc, ws + OFF_WV1, nullptr, nullptr, v,  1024, 1024);
    flash_mma_kernel<<<dim3(16, 64), blk, FSM>>>(q, kT, v, o2, 1);
    hf_gemm<-1, false, true, false><<<g1024, blk, SMH>>>(o2, ws + OFF_WO1, nullptr, outEnc, t1, 1024, 1024);
    ln_part_kernel<<<256, blk>>>(t1);
    ln_final_kernel<<<1, 32>>>();
    ln_apply_kernel<<<4096, blk>>>(t1, ln1w, ln1b, n1);

    // ---- MHA2 (cross) ----
    hf_gemm<0, false, false, false><<<g1024, blk, SMH>>>(n1,       ws + OFF_WQ2, nullptr, nullptr, q,  1024, 1024);
    hf_gemm<1, false, false, false><<<g1024, blk, SMH>>>(inputRes, ws + OFF_WK2, nullptr, nullptr, kT, 1024, 1024);
    hf_gemm<0, false, false, false><<<g1024, blk, SMH>>>(inputRes, ws + OFF_WV2, nullptr, nullptr, v,  1024, 1024);
    flash_mma_kernel<<<dim3(16, 64), blk, FSM>>>(q, kT, v, o2, 0);
    hf_gemm<-1, false, true, false><<<g1024, blk, SMH>>>(o2, ws + OFF_WO2, nullptr, outEnc, t1, 1024, 1024);
    ln_part_kernel<<<256, blk>>>(t1);
    ln_final_kernel<<<1, 32>>>();
    ln_apply_kernel<<<4096, blk>>>(t1, ln2w, ln2b, n2);

    // ---- FFN ----
    hf_gemm<-1, true, false, true ><<<g2048, blk, SMH>>>(n2,  ws + OFF_W1, b1, nullptr, fc1, 2048, 1024);
    hf_gemm<-1, true, true,  false><<<g1024, blk, SMH>>>(fc1, ws + OFF_W2, b2, n2,      t1,  1024, 2048);
    ln_part_kernel<<<256, blk>>>(t1);
    ln_final_kernel<<<1, 32>>>();
    ln_apply_kernel<<<4096, blk>>>(t1, ln3w, ln3b, out);
}

// round 9
// speedup vs baseline: 2.2915x; 1.2408x over previous
#include <cuda_runtime.h>
#include <cuda_fp16.h>
#include <math.h>
#include <stdint.h>

#define N_ELEM 4194304  // 4*1024*1024

// ---------------- scratch (device globals) ----------------------------------
__device__ float  g_q [N_ELEM];
__device__ float  g_kT[N_ELEM];
__device__ float  g_v [N_ELEM];
__device__ float  g_o2[N_ELEM];
__device__ float  g_t1[N_ELEM];
__device__ float  g_n1[N_ELEM];
__device__ float  g_n2[N_ELEM];
__device__ float  g_fc1[4096 * 2048];
__device__ double g_part[256][2];
__device__ float  g_stats[4][2];
// split fp16 weight planes: per weight [2][N][K]
__device__ __align__(16) __half g_ws[25165824];  // 48 MB

#define OFF_WQ1 0
#define OFF_WK1 2097152
#define OFF_WV1 4194304
#define OFF_WO1 6291456
#define OFF_WQ2 8388608
#define OFF_WK2 10485760
#define OFF_WV2 12582912
#define OFF_WO2 14680064
#define OFF_W1  16777216
#define OFF_W2  20971520

// ---------------- PTX helpers -------------------------------------------------
__device__ __forceinline__ void mma_f16(float* c, const unsigned* a, const unsigned* b) {
    asm volatile(
        "mma.sync.aligned.m16n8k16.row.col.f32.f16.f16.f32 "
        "{%0,%1,%2,%3}, {%4,%5,%6,%7}, {%8,%9}, {%0,%1,%2,%3};\n"
        : "+f"(c[0]), "+f"(c[1]), "+f"(c[2]), "+f"(c[3])
        : "r"(a[0]), "r"(a[1]), "r"(a[2]), "r"(a[3]), "r"(b[0]), "r"(b[1]));
}
__device__ __forceinline__ unsigned pack_h2(float a, float b) {
    __half2 h = __floats2half2_rn(a, b);
    return *(unsigned*)&h;
}
__device__ __forceinline__ void ldsm4(unsigned* r, uint32_t a) {
    asm volatile("ldmatrix.sync.aligned.m8n8.x4.shared.b16 {%0,%1,%2,%3}, [%4];"
        : "=r"(r[0]), "=r"(r[1]), "=r"(r[2]), "=r"(r[3]) : "r"(a));
}
__device__ __forceinline__ void cp16(uint32_t dst, const void* src) {
    asm volatile("cp.async.cg.shared.global [%0], [%1], 16;" :: "r"(dst), "l"(src));
}
#define CP_COMMIT() asm volatile("cp.async.commit_group;" ::: "memory")
#define CP_WAIT0()  asm volatile("cp.async.wait_group 0;" ::: "memory")

// ---------------- weight transpose + 2-way fp16 split ------------------------
// out[p][n][k] = plane p of W_logical[k][n]
struct W8Pack { const float* w[8]; };

__device__ __forceinline__ void wsplit_body(const float* __restrict__ W,
                                            __half* __restrict__ out,
                                            int N, int K, bool proj,
                                            int n0, int k0, int tid)
{
    __shared__ float t[64][65];
#pragma unroll
    for (int r = 0; r < 4; r++) {
        const int flat = tid + (r << 8);
        const int kr = flat >> 4, nc = (flat & 15) << 2;
        const float* src;
        if (proj) src = W + ((size_t)((n0 + nc) >> 6) << 16) + ((size_t)(k0 + kr) << 6) + ((n0 + nc) & 63);
        else      src = W + (size_t)(k0 + kr) * N + n0 + nc;
        float4 v = *(const float4*)src;
        t[kr][nc] = v.x; t[kr][nc + 1] = v.y; t[kr][nc + 2] = v.z; t[kr][nc + 3] = v.w;
    }
    __syncthreads();
    const size_t ps = (size_t)N * K;
#pragma unroll
    for (int r = 0; r < 4; r++) {
        const int flat = tid + (r << 8);
        const int nr = flat >> 4, kc = (flat & 15) << 2;
        unsigned short u0[4], u1[4];
#pragma unroll
        for (int j = 0; j < 4; j++) {
            float x = t[kc + j][nr];
            __half h0 = __float2half_rn(x);
            float r1 = x - __half2float(h0);
            u0[j] = __half_as_ushort(h0);
            u1[j] = __half_as_ushort(__float2half_rn(r1));
        }
        const size_t dst = (size_t)(n0 + nr) * K + k0 + kc;
        *(uint2*)(out + dst)      = make_uint2(u0[0] | (u0[1] << 16), u0[2] | (u0[3] << 16));
        *(uint2*)(out + ps + dst) = make_uint2(u1[0] | (u1[1] << 16), u1[2] | (u1[3] << 16));
    }
}

// 8 E x E attention weights in one launch (z selects weight)
__global__ __launch_bounds__(256)
void wsplit8_kernel(W8Pack pk, __half* __restrict__ out)
{
    const int z = blockIdx.z;
    const bool proj = (z & 3) != 3;  // q,k,v proj layout; o plain
    wsplit_body(pk.w[z], out + (size_t)z * 2097152, 1024, 1024, proj,
                blockIdx.x << 6, blockIdx.y << 6, threadIdx.x);
}

__global__ __launch_bounds__(256)
void wsplit_kernel(const float* __restrict__ W, __half* __restrict__ out, int N, int K)
{
    wsplit_body(W, out, N, K, false, blockIdx.x << 6, blockIdx.y << 6, threadIdx.x);
}

// ---------------- fp16 2-plane tensor-core GEMM v2 ---------------------------
// 2-stage cp.async pipeline, ldmatrix frags, fragment reuse across passes.
// smem per stage (bytes): Ah 10240 | Al 10240 | Bh 10240 | Bl 10240 = 40960.
template<int MODE, bool BIAS, bool RES, bool RELU>
__global__ __launch_bounds__(256, 2)
void hf_gemm(const float* __restrict__ A, const __half* __restrict__ Bp,
             const float* __restrict__ bias, const float* __restrict__ res,
             float* __restrict__ C, int N, int K)
{
    extern __shared__ __half smp[];
    const uint32_t sbase = (uint32_t)__cvta_generic_to_shared(smp);

    const int tid  = threadIdx.x;
    const int lane = tid & 31, wid = tid >> 5;
    const int g = lane >> 2, tig = lane & 3;
    const int quad = lane >> 3, rr = lane & 7;
    const int wm = wid >> 2, wn = wid & 3;
    const int m0 = blockIdx.y << 7, n0 = blockIdx.x << 7;
    const size_t bstride = (size_t)N * K;
    const int nstage = K >> 5;

    float acc[4][4][4];
#pragma unroll
    for (int mt = 0; mt < 4; mt++)
#pragma unroll
        for (int nt = 0; nt < 4; nt++)
#pragma unroll
            for (int c = 0; c < 4; c++) acc[mt][nt][c] = 0.f;

    // per-thread ldmatrix offsets (bytes)
    const int aoff = ((rr + ((quad & 1) << 3)) * 40 + ((quad >> 1) << 3)) << 1;
    const int boff = ((rr + ((quad >> 1) << 3)) * 40 + ((quad & 1) << 3)) << 1;

    // ---- prologue: B(0) via cp.async, A(0) direct ----
#pragma unroll
    for (int p = 0; p < 2; p++)
#pragma unroll
        for (int r = 0; r < 2; r++) {
            const int flat = tid + (r << 8);
            const int row = flat >> 2, cs = (flat & 3) << 3;
            cp16(sbase + 20480 + p * 10240 + ((row * 40 + cs) << 1),
                 Bp + (size_t)p * bstride + (size_t)(n0 + row) * K + cs);
        }
    CP_COMMIT();
#pragma unroll
    for (int r = 0; r < 4; r++) {
        const int flat = tid + (r << 8);
        const int row = flat >> 3, c4 = (flat & 7) << 2;
        float4 av = *(const float4*)(A + (size_t)(m0 + row) * K + c4);
        float x[4] = {av.x, av.y, av.z, av.w};
        unsigned short u0[4], u1[4];
#pragma unroll
        for (int j = 0; j < 4; j++) {
            __half h0 = __float2half_rn(x[j]);
            float r1 = x[j] - __half2float(h0);
            u0[j] = __half_as_ushort(h0);
            u1[j] = __half_as_ushort(__float2half_rn(r1));
        }
        const int off = row * 40 + c4;
        *(uint2*)(smp + off)        = make_uint2(u0[0] | (u0[1] << 16), u0[2] | (u0[3] << 16));
        *(uint2*)(smp + 5120 + off) = make_uint2(u1[0] | (u1[1] << 16), u1[2] | (u1[3] << 16));
    }

    for (int s = 0; s < nstage; s++) {
        const uint32_t stg = (uint32_t)(s & 1) * 40960u;
        CP_WAIT0();            // B(s) landed
        __syncthreads();       // A(s) stores + all warps past stage s-1

        // ---- issue fills for stage s+1 ----
        float4 pa2[4];
        const int kn = (s + 1) << 5;
        const bool more = kn < K;
        if (more) {
            const uint32_t nst = (uint32_t)((s + 1) & 1) * 40960u;
#pragma unroll
            for (int p = 0; p < 2; p++)
#pragma unroll
                for (int r = 0; r < 2; r++) {
                    const int flat = tid + (r << 8);
                    const int row = flat >> 2, cs = (flat & 3) << 3;
                    cp16(sbase + nst + 20480 + p * 10240 + ((row * 40 + cs) << 1),
                         Bp + (size_t)p * bstride + (size_t)(n0 + row) * K + kn + cs);
                }
            CP_COMMIT();
#pragma unroll
            for (int r = 0; r < 4; r++) {
                const int flat = tid + (r << 8);
                const int row = flat >> 3, c4 = (flat & 7) << 2;
                pa2[r] = *(const float4*)(A + (size_t)(m0 + row) * K + kn + c4);
            }
        }

        // ---- compute stage s ----
        const uint32_t Ab = sbase + stg;
        const uint32_t Bb = sbase + stg + 20480;
#pragma unroll
        for (int kt = 0; kt < 2; kt++) {
            const int kbB = kt << 5;  // kt*16 halves *2 bytes
            unsigned a0[4][4], b0[4][2], bx[4][2], a1[4][4];
            // A plane 0
#pragma unroll
            for (int mt = 0; mt < 4; mt++)
                ldsm4(a0[mt], Ab + ((((wm << 6) + (mt << 4)) * 40) << 1) + kbB + aoff);
            // B plane 0
#pragma unroll
            for (int nh = 0; nh < 2; nh++) {
                unsigned t4[4];
                ldsm4(t4, Bb + ((((wn << 5) + (nh << 4)) * 40) << 1) + kbB + boff);
                b0[2 * nh][0] = t4[0]; b0[2 * nh][1] = t4[1];
                b0[2 * nh + 1][0] = t4[2]; b0[2 * nh + 1][1] = t4[3];
            }
#pragma unroll
            for (int mt = 0; mt < 4; mt++)
#pragma unroll
                for (int nt = 0; nt < 4; nt++)
                    mma_f16(acc[mt][nt], a0[mt], b0[nt]);   // Ah*Bh
            // B plane 1
#pragma unroll
            for (int nh = 0; nh < 2; nh++) {
                unsigned t4[4];
                ldsm4(t4, Bb + 10240 + ((((wn << 5) + (nh << 4)) * 40) << 1) + kbB + boff);
                bx[2 * nh][0] = t4[0]; bx[2 * nh][1] = t4[1];
                bx[2 * nh + 1][0] = t4[2]; bx[2 * nh + 1][1] = t4[3];
            }
#pragma unroll
            for (int mt = 0; mt < 4; mt++)
#pragma unroll
                for (int nt = 0; nt < 4; nt++)
                    mma_f16(acc[mt][nt], a0[mt], bx[nt]);   // Ah*Bl
            // A plane 1
#pragma unroll
            for (int mt = 0; mt < 4; mt++)
                ldsm4(a1[mt], Ab + 10240 + ((((wm << 6) + (mt << 4)) * 40) << 1) + kbB + aoff);
#pragma unroll
            for (int mt = 0; mt < 4; mt++)
#pragma unroll
                for (int nt = 0; nt < 4; nt++)
                    mma_f16(acc[mt][nt], a1[mt], b0[nt]);   // Al*Bh
        }

        // ---- split-store A(s+1) into the other stage ----
        if (more) {
            __half* An = smp + ((s + 1) & 1) * 20480;
#pragma unroll
            for (int r = 0; r < 4; r++) {
                const int flat = tid + (r << 8);
                const int row = flat >> 3, c4 = (flat & 7) << 2;
                float x[4] = {pa2[r].x, pa2[r].y, pa2[r].z, pa2[r].w};
                unsigned short u0[4], u1[4];
#pragma unroll
                for (int j = 0; j < 4; j++) {
                    __half h0 = __float2half_rn(x[j]);
                    float r1 = x[j] - __half2float(h0);
                    u0[j] = __half_as_ushort(h0);
                    u1[j] = __half_as_ushort(__float2half_rn(r1));
                }
                const int off = row * 40 + c4;
                *(uint2*)(An + off)        = make_uint2(u0[0] | (u0[1] << 16), u0[2] | (u0[3] << 16));
                *(uint2*)(An + 5120 + off) = make_uint2(u1[0] | (u1[1] << 16), u1[2] | (u1[3] << 16));
            }
        }
    }

    // ---------------- epilogue ----------------
#pragma unroll
    for (int mt = 0; mt < 4; mt++) {
#pragma unroll
        for (int nt = 0; nt < 4; nt++) {
            const int m = m0 + (wm << 6) + (mt << 4) + g;
            const int n = n0 + (wn << 5) + (nt << 3) + (tig << 1);
            const float* c = acc[mt][nt];
            float2 v0 = make_float2(c[0], c[1]);
            float2 v1 = make_float2(c[2], c[3]);

            if constexpr (MODE < 0) {
                if (BIAS) {
                    float2 bv = *(const float2*)(bias + n);
                    v0.x += bv.x; v0.y += bv.y; v1.x += bv.x; v1.y += bv.y;
                }
                if (RES) {
                    float2 r0 = *(const float2*)(res + (size_t)m * N + n);
                    float2 r1 = *(const float2*)(res + (size_t)(m + 8) * N + n);
                    v0.x += r0.x; v0.y += r0.y; v1.x += r1.x; v1.y += r1.y;
                }
                if (RELU) {
                    v0.x = fmaxf(v0.x, 0.f); v0.y = fmaxf(v0.y, 0.f);
                    v1.x = fmaxf(v1.x, 0.f); v1.y = fmaxf(v1.y, 0.f);
                }
                *(float2*)(C + (size_t)m * N + n) = v0;
                *(float2*)(C + (size_t)(m + 8) * N + n) = v1;
            } else if constexpr (MODE == 0) {
                const int b = m >> 10, s = m & 1023;
                const int h = n >> 6, d = n & 63;
                const size_t hb = (size_t)(h * 4 + b);
                *(float2*)(C + (((hb << 10) + s) << 6) + d) = v0;
                *(float2*)(C + (((hb << 10) + s + 8) << 6) + d) = v1;
            } else {
                const int b = m >> 10, s = m & 1023;
                const int h = n >> 6, d = n & 63;
                const size_t hb = (size_t)(h * 4 + b);
                const int t0a = ((s & 15) << 6) | d;
                const int t0b = (((s + 8) & 15) << 6) | d;
                C[((hb << 10) + t0a)     * 64 + (s >> 4)]       = c[0];
                C[((hb << 10) + t0a + 1) * 64 + (s >> 4)]       = c[1];
                C[((hb << 10) + t0b)     * 64 + ((s + 8) >> 4)] = c[2];
                C[((hb << 10) + t0b + 1) * 64 + ((s + 8) >> 4)] = c[3];
            }
        }
    }
}

// ---------------- tensor-core flash attention (unchanged from R8) ------------
__global__ __launch_bounds__(256)
void flash_mma_kernel(const float* __restrict__ Q, const float* __restrict__ KT,
                      const float* __restrict__ V, float* __restrict__ O2, int causal)
{
    extern __shared__ char fsm[];
    __half* Kh = (__half*)fsm;
    __half* Kl = Kh + 4608;
    __half* Vh = Kh + 9216;
    __half* Vl = Kh + 13824;
    float* smax = (float*)(fsm + 36864);
    float* ssum = smax + 128;
    float* sm_o = (float*)fsm;

    const int tid = threadIdx.x;
    const int lane = tid & 31, wid = tid >> 5;
    const int g = lane >> 2, tig = lane & 3;
    const int wm = wid >> 1, wn = wid & 1;
    const int s0 = blockIdx.x << 6;
    const int hb = blockIdx.y;
    const size_t base = (size_t)hb << 16;
    const int mrow = (wm << 4) + g;

#pragma unroll
    for (int it = 0; it < 4; it++) {
        const int flat = tid + (it << 8);
        const int r = flat >> 4, c4 = (flat & 15) << 2;
        float4 qv = *(const float4*)(Q + base + ((size_t)(s0 + r) << 6) + c4);
        float x[4] = {qv.x * 0.125f, qv.y * 0.125f, qv.z * 0.125f, qv.w * 0.125f};
        unsigned short u0[4], u1[4];
#pragma unroll
        for (int j = 0; j < 4; j++) {
            __half h0 = __float2half_rn(x[j]);
            float r1 = x[j] - __half2float(h0);
            u0[j] = __half_as_ushort(h0);
            u1[j] = __half_as_ushort(__float2half_rn(r1));
        }
        *(uint2*)&Kh[r * 72 + c4] = make_uint2(u0[0] | (u0[1] << 16), u0[2] | (u0[3] << 16));
        *(uint2*)&Kl[r * 72 + c4] = make_uint2(u1[0] | (u1[1] << 16), u1[2] | (u1[3] << 16));
    }
    __syncthreads();

    unsigned qh[4][4], ql[4][4];
#pragma unroll
    for (int kt = 0; kt < 4; kt++) {
        const int kb = kt << 4;
        qh[kt][0] = *(const unsigned*)&Kh[mrow * 72 + kb + (tig << 1)];
        qh[kt][1] = *(const unsigned*)&Kh[(mrow + 8) * 72 + kb + (tig << 1)];
        qh[kt][2] = *(const unsigned*)&Kh[mrow * 72 + kb + 8 + (tig << 1)];
        qh[kt][3] = *(const unsigned*)&Kh[(mrow + 8) * 72 + kb + 8 + (tig << 1)];
        ql[kt][0] = *(const unsigned*)&Kl[mrow * 72 + kb + (tig << 1)];
        ql[kt][1] = *(const unsigned*)&Kl[(mrow + 8) * 72 + kb + (tig << 1)];
        ql[kt][2] = *(const unsigned*)&Kl[mrow * 72 + kb + 8 + (tig << 1)];
        ql[kt][3] = *(const unsigned*)&Kl[(mrow + 8) * 72 + kb + 8 + (tig << 1)];
    }

    float o[8][4];
#pragma unroll
    for (int nt = 0; nt < 8; nt++)
#pragma unroll
        for (int c = 0; c < 4; c++) o[nt][c] = 0.f;
    float m0 = -INFINITY, m1 = -INFINITY, l0 = 0.f, l1 = 0.f;

    const int row0 = s0 + mrow, row1 = row0 + 8;
    const int ntiles = causal ? ((int)blockIdx.x + 1) : 16;

    for (int jt = 0; jt < ntiles; jt++) {
        const int t0 = jt << 6;
        __syncthreads();

#pragma unroll
        for (int it = 0; it < 4; it++) {
            const int flat = tid + (it << 8);
            const int r = flat >> 4, c4 = (flat & 15) << 2;
            float4 kv = *(const float4*)(KT + base + ((size_t)(t0 + r) << 6) + c4);
            float x[4] = {kv.x, kv.y, kv.z, kv.w};
            unsigned short u0[4], u1[4];
#pragma unroll
            for (int j = 0; j < 4; j++) {
                __half h0 = __float2half_rn(x[j]);
                float r1 = x[j] - __half2float(h0);
                u0[j] = __half_as_ushort(h0);
                u1[j] = __half_as_ushort(__float2half_rn(r1));
            }
            *(uint2*)&Kh[r * 72 + c4] = make_uint2(u0[0] | (u0[1] << 16), u0[2] | (u0[3] << 16));
            *(uint2*)&Kl[r * 72 + c4] = make_uint2(u1[0] | (u1[1] << 16), u1[2] | (u1[3] << 16));
        }
#pragma unroll
        for (int it = 0; it < 4; it++) {
            const int flat = tid + (it << 8);
            const int tr = flat >> 4, dv4 = (flat & 15) << 2;
            float4 vv = *(const float4*)(V + base + ((size_t)(t0 + tr) << 6) + dv4);
            float x[4] = {vv.x, vv.y, vv.z, vv.w};
#pragma unroll
            for (int j = 0; j < 4; j++) {
                const int dv = dv4 + j;
                const int sw = ((dv >> 2) & 7) << 3;
                const int idx = dv * 72 + (tr ^ sw);
                __half h0 = __float2half_rn(x[j]);
                float r1 = x[j] - __half2float(h0);
                Vh[idx] = h0;
                Vl[idx] = __float2half_rn(r1);
            }
        }
        __syncthreads();

        float sc[4][4];
#pragma unroll
        for (int nt = 0; nt < 4; nt++)
#pragma unroll
            for (int c = 0; c < 4; c++) sc[nt][c] = 0.f;
#pragma unroll
        for (int kt = 0; kt < 4; kt++) {
            const int kb = kt << 4;
#pragma unroll
            for (int nt = 0; nt < 4; nt++) {
                const int nr = (wn << 5) + (nt << 3) + g;
                unsigned b[2];
                b[0] = *(const unsigned*)&Kh[nr * 72 + kb + (tig << 1)];
                b[1] = *(const unsigned*)&Kh[nr * 72 + kb + 8 + (tig << 1)];
                mma_f16(sc[nt], qh[kt], b);
                mma_f16(sc[nt], ql[kt], b);
            }
        }
#pragma unroll
        for (int kt = 0; kt < 4; kt++) {
            const int kb = kt << 4;
#pragma unroll
            for (int nt = 0; nt < 4; nt++) {
                const int nr = (wn << 5) + (nt << 3) + g;
                unsigned b[2];
                b[0] = *(const unsigned*)&Kl[nr * 72 + kb + (tig << 1)];
                b[1] = *(const unsigned*)&Kl[nr * 72 + kb + 8 + (tig << 1)];
                mma_f16(sc[nt], qh[kt], b);
            }
        }

        float mx0 = -INFINITY, mx1 = -INFINITY;
#pragma unroll
        for (int nt = 0; nt < 4; nt++) {
            const int col = t0 + (wn << 5) + (nt << 3) + (tig << 1);
            if (causal) {
                if (col > row0)     sc[nt][0] = -INFINITY;
                if (col + 1 > row0) sc[nt][1] = -INFINITY;
                if (col > row1)     sc[nt][2] = -INFINITY;
                if (col + 1 > row1) sc[nt][3] = -INFINITY;
            }
            mx0 = fmaxf(mx0, fmaxf(sc[nt][0], sc[nt][1]));
            mx1 = fmaxf(mx1, fmaxf(sc[nt][2], sc[nt][3]));
        }
        mx0 = fmaxf(mx0, __shfl_xor_sync(0xffffffffu, mx0, 1));
        mx0 = fmaxf(mx0, __shfl_xor_sync(0xffffffffu, mx0, 2));
        mx1 = fmaxf(mx1, __shfl_xor_sync(0xffffffffu, mx1, 1));
        mx1 = fmaxf(mx1, __shfl_xor_sync(0xffffffffu, mx1, 2));
        smax[(wn << 6) + mrow] = mx0;
        smax[(wn << 6) + mrow + 8] = mx1;
        __syncthreads();

        const float mn0 = fmaxf(m0, fmaxf(smax[mrow], smax[64 + mrow]));
        const float mn1 = fmaxf(m1, fmaxf(smax[mrow + 8], smax[64 + mrow + 8]));
        const float cr0 = __expf(m0 - mn0);
        const float cr1 = __expf(m1 - mn1);
        m0 = mn0; m1 = mn1;
#pragma unroll
        for (int nt = 0; nt < 8; nt++) {
            o[nt][0] *= cr0; o[nt][1] *= cr0;
            o[nt][2] *= cr1; o[nt][3] *= cr1;
        }
        float p[4][4];
        float rs0 = 0.f, rs1 = 0.f;
#pragma unroll
        for (int nt = 0; nt < 4; nt++) {
            p[nt][0] = __expf(sc[nt][0] - mn0);
            p[nt][1] = __expf(sc[nt][1] - mn0);
            p[nt][2] = __expf(sc[nt][2] - mn1);
            p[nt][3] = __expf(sc[nt][3] - mn1);
            rs0 += p[nt][0] + p[nt][1];
            rs1 += p[nt][2] + p[nt][3];
        }
        rs0 += __shfl_xor_sync(0xffffffffu, rs0, 1);
        rs0 += __shfl_xor_sync(0xffffffffu, rs0, 2);
        rs1 += __shfl_xor_sync(0xffffffffu, rs1, 1);
        rs1 += __shfl_xor_sync(0xffffffffu, rs1, 2);
        ssum[(wn << 6) + mrow] = rs0;
        ssum[(wn << 6) + mrow + 8] = rs1;
        __syncthreads();
        l0 = l0 * cr0 + ssum[mrow] + ssum[64 + mrow];
        l1 = l1 * cr1 + ssum[mrow + 8] + ssum[64 + mrow + 8];

        unsigned ah[2][4], al[2][4];
#pragma unroll
        for (int kc = 0; kc < 2; kc++) {
            const int ta = kc << 1, tb = ta + 1;
            float h00 = __half2float(__float2half_rn(p[ta][0]));
            float h01 = __half2float(__float2half_rn(p[ta][1]));
            float h02 = __half2float(__float2half_rn(p[ta][2]));
            float h03 = __half2float(__float2half_rn(p[ta][3]));
            float h10 = __half2float(__float2half_rn(p[tb][0]));
            float h11 = __half2float(__float2half_rn(p[tb][1]));
            float h12 = __half2float(__float2half_rn(p[tb][2]));
            float h13 = __half2float(__float2half_rn(p[tb][3]));
            ah[kc][0] = pack_h2(h00, h01);
            ah[kc][1] = pack_h2(h02, h03);
            ah[kc][2] = pack_h2(h10, h11);
            ah[kc][3] = pack_h2(h12, h13);
            al[kc][0] = pack_h2(p[ta][0] - h00, p[ta][1] - h01);
            al[kc][1] = pack_h2(p[ta][2] - h02, p[ta][3] - h03);
            al[kc][2] = pack_h2(p[tb][0] - h10, p[tb][1] - h11);
            al[kc][3] = pack_h2(p[tb][2] - h12, p[tb][3] - h13);
        }

#pragma unroll
        for (int nt = 0; nt < 8; nt++) {
            const int dv = (nt << 3) + g;
            const int sw = ((dv >> 2) & 7) << 3;
            const int rb = dv * 72;
#pragma unroll
            for (int kc = 0; kc < 2; kc++) {
                const int kg = (wn << 5) + (kc << 4);
                unsigned vb[2], wb[2];
                vb[0] = *(const unsigned*)&Vh[rb + ((kg ^ sw) + (tig << 1))];
                vb[1] = *(const unsigned*)&Vh[rb + (((kg + 8) ^ sw) + (tig << 1))];
                mma_f16(o[nt], ah[kc], vb);
                mma_f16(o[nt], al[kc], vb);
                wb[0] = *(const unsigned*)&Vl[rb + ((kg ^ sw) + (tig << 1))];
                wb[1] = *(const unsigned*)&Vl[rb + (((kg + 8) ^ sw) + (tig << 1))];
                mma_f16(o[nt], ah[kc], wb);
            }
        }
    }

    const float il0 = 1.f / l0, il1 = 1.f / l1;
#pragma unroll
    for (int nt = 0; nt < 8; nt++) {
        o[nt][0] *= il0; o[nt][1] *= il0;
        o[nt][2] *= il1; o[nt][3] *= il1;
    }
    __syncthreads();
    float* po = sm_o + wn * 4608;
#pragma unroll
    for (int nt = 0; nt < 8; nt++) {
        const int dv = (nt << 3) + (tig << 1);
        *(float2*)&po[mrow * 72 + dv]       = make_float2(o[nt][0], o[nt][1]);
        *(float2*)&po[(mrow + 8) * 72 + dv] = make_float2(o[nt][2], o[nt][3]);
    }
    __syncthreads();
    if (wn == 0) {
        const int h = hb >> 2, b = hb & 3;
        const int r = lane >> 1;
        const int dvh = (lane & 1) << 5;
        const int row = (wm << 4) + r;
        const int s = s0 + row;
        const size_t orow = ((size_t)((h >> 2) * 1024 + (h & 3) * 256 + b * 64 + (s >> 4)) << 10)
                          + ((s & 15) << 6);
#pragma unroll
        for (int i = 0; i < 8; i++) {
            const int dv = dvh + (i << 2);
            float4 a = *(const float4*)&sm_o[row * 72 + dv];
            float4 bb = *(const float4*)&sm_o[4608 + row * 72 + dv];
            float4 vv = make_float4(a.x + bb.x, a.y + bb.y, a.z + bb.z, a.w + bb.w);
            *(float4*)(O2 + orow + dv) = vv;
        }
    }
}

// ---------------- LayerNorm over (S,E) slab per batch ------------------------
__global__ void ln_part_kernel(const float* __restrict__ X)
{
    __shared__ double sd[256];
    __shared__ double sq[256];
    const int tid = threadIdx.x;
    const float4* p = (const float4*)(X + ((size_t)blockIdx.x << 14));
    float s = 0.f, q = 0.f;
#pragma unroll
    for (int it = 0; it < 16; it++) {
        float4 v = p[it * 256 + tid];
        s += v.x + v.y + v.z + v.w;
        q += v.x * v.x + v.y * v.y + v.z * v.z + v.w * v.w;
    }
    sd[tid] = (double)s; sq[tid] = (double)q;
    __syncthreads();
    for (int off = 128; off > 0; off >>= 1) {
        if (tid < off) { sd[tid] += sd[tid + off]; sq[tid] += sq[tid + off]; }
        __syncthreads();
    }
    if (tid == 0) { g_part[blockIdx.x][0] = sd[0]; g_part[blockIdx.x][1] = sq[0]; }
}

__global__ void ln_final_kernel()
{
    const int b = threadIdx.x;
    if (b < 4) {
        double s = 0.0, q = 0.0;
        for (int i = 0; i < 64; i++) { s += g_part[b * 64 + i][0]; q += g_part[b * 64 + i][1]; }
        const double inv_n = 1.0 / 1048576.0;
        const double mean = s * inv_n;
        const double var = q * inv_n - mean * mean;
        g_stats[b][0] = (float)mean;
        g_stats[b][1] = (float)(1.0 / sqrt(var + 1e-5));
    }
}

__global__ void ln_apply_kernel(const float* __restrict__ X, const float* __restrict__ w,
                                const float* __restrict__ bb, float* __restrict__ Y)
{
    const size_t i = ((size_t)blockIdx.x * 256 + threadIdx.x) << 2;
    const int b = (int)(i >> 20);
    const float mean = g_stats[b][0], inv = g_stats[b][1];
    const size_t wi = i & 1048575;
    float4 x = *(const float4*)(X + i);
    float4 wv = *(const float4*)(w + wi);
    float4 bv = *(const float4*)(bb + wi);
    float4 y;
    y.x = (x.x - mean) * inv * wv.x + bv.x;
    y.y = (x.y - mean) * inv * wv.y + bv.y;
    y.z = (x.z - mean) * inv * wv.z + bv.z;
    y.w = (x.w - mean) * inv * wv.w + bv.w;
    *(float4*)(Y + i) = y;
}

// ---------------- driver -----------------------------------------------------
extern "C" void kernel_launch(void* const* d_in, const int* in_sizes, int n_in,
                              void* d_out, int out_size)
{
    const float* inputRes = (const float*)d_in[0];
    const float* outEnc   = (const float*)d_in[1];
    const float* Wq1 = (const float*)d_in[2];
    const float* Wk1 = (const float*)d_in[3];
    const float* Wv1 = (const float*)d_in[4];
    const float* Wo1 = (const float*)d_in[5];
    const float* Wq2 = (const float*)d_in[6];
    const float* Wk2 = (const float*)d_in[7];
    const float* Wv2 = (const float*)d_in[8];
    const float* Wo2 = (const float*)d_in[9];
    const float* ln1w = (const float*)d_in[10];
    const float* ln1b = (const float*)d_in[11];
    const float* ln2w = (const float*)d_in[12];
    const float* ln2b = (const float*)d_in[13];
    const float* ln3w = (const float*)d_in[14];
    const float* ln3b = (const float*)d_in[15];
    const float* W1 = (const float*)d_in[16];
    const float* b1 = (const float*)d_in[17];
    const float* W2 = (const float*)d_in[18];
    const float* b2 = (const float*)d_in[19];
    float* out = (float*)d_out;

    float *q, *kT, *v, *o2, *t1, *n1, *n2, *fc1;
    __half* ws;
    cudaGetSymbolAddress((void**)&q,   g_q);
    cudaGetSymbolAddress((void**)&kT,  g_kT);
    cudaGetSymbolAddress((void**)&v,   g_v);
    cudaGetSymbolAddress((void**)&o2,  g_o2);
    cudaGetSymbolAddress((void**)&t1,  g_t1);
    cudaGetSymbolAddress((void**)&n1,  g_n1);
    cudaGetSymbolAddress((void**)&n2,  g_n2);
    cudaGetSymbolAddress((void**)&fc1, g_fc1);
    cudaGetSymbolAddress((void**)&ws,  g_ws);

    const int FSM = 37888;
    cudaFuncSetAttribute(flash_mma_kernel, cudaFuncAttributeMaxDynamicSharedMemorySize, FSM);

    const int SMH = 81920;  // 2 stages x 40960 B
    cudaFuncSetAttribute(hf_gemm<0, false, false, false>, cudaFuncAttributeMaxDynamicSharedMemorySize, SMH);
    cudaFuncSetAttribute(hf_gemm<1, false, false, false>, cudaFuncAttributeMaxDynamicSharedMemorySize, SMH);
    cudaFuncSetAttribute(hf_gemm<-1, false, true, false>, cudaFuncAttributeMaxDynamicSharedMemorySize, SMH);
    cudaFuncSetAttribute(hf_gemm<-1, true, false, true >, cudaFuncAttributeMaxDynamicSharedMemorySize, SMH);
    cudaFuncSetAttribute(hf_gemm<-1, true, true,  false>, cudaFuncAttributeMaxDynamicSharedMemorySize, SMH);

    dim3 blk(256);

    // ---- pre-split weights into transposed fp16 planes ----
    W8Pack pk;
    pk.w[0] = Wq1; pk.w[1] = Wk1; pk.w[2] = Wv1; pk.w[3] = Wo1;
    pk.w[4] = Wq2; pk.w[5] = Wk2; pk.w[6] = Wv2; pk.w[7] = Wo2;
    wsplit8_kernel<<<dim3(16, 16, 8), blk>>>(pk, ws);
    wsplit_kernel<<<dim3(32, 16), blk>>>(W1, ws + OFF_W1, 2048, 1024);
    wsplit_kernel<<<dim3(16, 32), blk>>>(W2, ws + OFF_W2, 1024, 2048);

    dim3 g1024(8, 32), g2048(16, 32);

    // ---- MHA1 (self, causal) ----
    hf_gemm<0, false, false, false><<<g1024, blk, SMH>>>(outEnc, ws + OFF_WQ1, nullptr, nullptr, q,  1024, 1024);
    hf_gemm<1, false, false, false><<<g1024, blk, SMH>>>(outEnc, ws + OFF_WK1, nullptr, nullptr, kT, 1024, 1024);
    hf_gemm<0, false, false, false><<<g1024, blk, SMH>>>(outEnc, ws + OFF_WV1, nullptr, nullptr, v,  1024, 1024);
    flash_mma_kernel<<<dim3(16, 64), blk, FSM>>>(q, kT, v, o2, 1);
    hf_gemm<-1, false, true, false><<<g1024, blk, SMH>>>(o2, ws + OFF_WO1, nullptr, outEnc, t1, 1024, 1024);
    ln_part_kernel<<<256, blk>>>(t1);
    ln_final_kernel<<<1, 32>>>();
    ln_apply_kernel<<<4096, blk>>>(t1, ln1w, ln1b, n1);

    // ---- MHA2 (cross) ----
    hf_gemm<0, false, false, false><<<g1024, blk, SMH>>>(n1,       ws + OFF_WQ2, nullptr, nullptr, q,  1024, 1024);
    hf_gemm<1, false, false, false><<<g1024, blk, SMH>>>(inputRes, ws + OFF_WK2, nullptr, nullptr, kT, 1024, 1024);
    hf_gemm<0, false, false, false><<<g1024, blk, SMH>>>(inputRes, ws + OFF_WV2, nullptr, nullptr, v,  1024, 1024);
    flash_mma_kernel<<<dim3(16, 64), blk, FSM>>>(q, kT, v, o2, 0);
    hf_gemm<-1, false, true, false><<<g1024, blk, SMH>>>(o2, ws + OFF_WO2, nullptr, outEnc, t1, 1024, 1024);
    ln_part_kernel<<<256, blk>>>(t1);
    ln_final_kernel<<<1, 32>>>();
    ln_apply_kernel<<<4096, blk>>>(t1, ln2w, ln2b, n2);

    // ---- FFN ----
    hf_gemm<-1, true, false, true ><<<g2048, blk, SMH>>>(n2,  ws + OFF_W1, b1, nullptr, fc1, 2048, 1024);
    hf_gemm<-1, true, true,  false><<<g1024, blk, SMH>>>(fc1, ws + OFF_W2, b2, n2,      t1,  1024, 2048);
    ln_part_kernel<<<256, blk>>>(t1);
    ln_final_kernel<<<1, 32>>>();
    ln_apply_kernel<<<4096, blk>>>(t1, ln3w, ln3b, out);
}